// round 12
// baseline (speedup 1.0000x reference)
#include <cuda_runtime.h>
#include <cuda_bf16.h>
#include <math.h>
#include <stdint.h>

// ---------------------------------------------------------------------------
// Problem constants
// ---------------------------------------------------------------------------
#define S_LEN     8192
#define T_LEN     256
#define NUM_HEADS 16
#define HEAD_DIM  64
#define INNER     1024
#define INNER3    3072
#define SPARSE_N  8
#define G_LEN     1024
#define STOT      1280
#define NJH       128
#define EPS_RMS   1e-5f
#define ATTN_SCALE 0.125f
#define SMAX      8.0f
#define ATT_ELEMS (NJH * STOT * HEAD_DIM)

// ---------------------------------------------------------------------------
// Static device scratch
// ---------------------------------------------------------------------------
__device__ float g_encpart[4 * T_LEN * INNER3];
__device__ float g_txtpart[4 * T_LEN * INNER];
__device__ float g_OA[ATT_ELEMS];

__device__ __nv_bfloat16 g_hs_h[S_LEN * INNER];
__device__ __nv_bfloat16 g_hs_l[S_LEN * INNER];
__device__ __nv_bfloat16 g_enc_h[T_LEN * INNER];
__device__ __nv_bfloat16 g_enc_l[T_LEN * INNER];
__device__ __nv_bfloat16 g_w_h[8 * INNER * INNER];
__device__ __nv_bfloat16 g_w_l[8 * INNER * INNER];
__device__ __nv_bfloat16 g_vis_h[S_LEN * INNER];
__device__ __nv_bfloat16 g_vis_l[S_LEN * INNER];
__device__ __nv_bfloat16 g_txt_h[T_LEN * INNER];
__device__ __nv_bfloat16 g_txt_l[T_LEN * INNER];
__device__ __nv_bfloat16 g_QAh[ATT_ELEMS];
__device__ __nv_bfloat16 g_QAl[ATT_ELEMS];
__device__ __nv_bfloat16 g_KAh[ATT_ELEMS];
__device__ __nv_bfloat16 g_KAl[ATT_ELEMS];
__device__ __nv_bfloat16 g_VAh[ATT_ELEMS];
__device__ __nv_bfloat16 g_VAl[ATT_ELEMS];

// ---------------------------------------------------------------------------
// Helpers
// ---------------------------------------------------------------------------
__device__ __forceinline__ uint32_t smem_u32(const void* p) {
    uint32_t a;
    asm("{ .reg .u64 t; cvta.to.shared.u64 t, %1; cvt.u32.u64 %0, t; }"
        : "=r"(a) : "l"(p));
    return a;
}

#define CP_ASYNC16(dst, src) \
    asm volatile("cp.async.cg.shared.global [%0], [%1], 16;" :: "r"(dst), "l"(src))
#define CP_COMMIT() asm volatile("cp.async.commit_group;" ::: "memory")
#define CP_WAIT0()  asm volatile("cp.async.wait_group 0;" ::: "memory")
#define CP_WAIT1()  asm volatile("cp.async.wait_group 1;" ::: "memory")
#define CP_WAIT2()  asm volatile("cp.async.wait_group 2;" ::: "memory")

__device__ __forceinline__ void ldsm_x4(uint32_t* r, uint32_t a) {
    asm volatile("ldmatrix.sync.aligned.m8n8.x4.shared.b16 {%0,%1,%2,%3}, [%4];"
        : "=r"(r[0]), "=r"(r[1]), "=r"(r[2]), "=r"(r[3]) : "r"(a));
}
__device__ __forceinline__ void ldsm_x4_t(uint32_t* r, uint32_t a) {
    asm volatile("ldmatrix.sync.aligned.m8n8.x4.trans.shared.b16 {%0,%1,%2,%3}, [%4];"
        : "=r"(r[0]), "=r"(r[1]), "=r"(r[2]), "=r"(r[3]) : "r"(a));
}
__device__ __forceinline__ void mma16816(float* c, const uint32_t* a, const uint32_t* b) {
    asm volatile(
        "mma.sync.aligned.m16n8k16.row.col.f32.bf16.bf16.f32 "
        "{%0,%1,%2,%3}, {%4,%5,%6,%7}, {%8,%9}, {%0,%1,%2,%3};"
        : "+f"(c[0]), "+f"(c[1]), "+f"(c[2]), "+f"(c[3])
        : "r"(a[0]), "r"(a[1]), "r"(a[2]), "r"(a[3]), "r"(b[0]), "r"(b[1]));
}

__device__ __forceinline__ uint32_t packbf(__nv_bfloat16 x, __nv_bfloat16 y) {
    return (uint32_t)__bfloat16_as_ushort(x) | ((uint32_t)__bfloat16_as_ushort(y) << 16);
}
__device__ __forceinline__ void split2(float x, float y, uint32_t& hi, uint32_t& lo) {
    __nv_bfloat16 hx = __float2bfloat16(x), hy = __float2bfloat16(y);
    __nv_bfloat16 lx = __float2bfloat16(x - __bfloat162float(hx));
    __nv_bfloat16 ly = __float2bfloat16(y - __bfloat162float(hy));
    hi = packbf(hx, hy);
    lo = packbf(lx, ly);
}
__device__ __forceinline__ void store_split(__nv_bfloat16* ph, __nv_bfloat16* pl,
                                            size_t idx, float v) {
    __nv_bfloat16 h = __float2bfloat16(v);
    ph[idx] = h;
    pl[idx] = __float2bfloat16(v - __bfloat162float(h));
}
__device__ __forceinline__ float warp_sum32(float v) {
#pragma unroll
    for (int o = 16; o > 0; o >>= 1)
        v += __shfl_xor_sync(0xffffffffu, v, o);
    return v;
}

__device__ __forceinline__ void cvt4(const float* __restrict__ src,
                                     __nv_bfloat16* __restrict__ hi,
                                     __nv_bfloat16* __restrict__ lo,
                                     int base)
{
    float4 v0 = ((const float4*)src)[base];
    float4 v1 = ((const float4*)src)[base + 256];
    float4 v2 = ((const float4*)src)[base + 512];
    float4 v3 = ((const float4*)src)[base + 768];
    uint32_t a, b, c, d;
    split2(v0.x, v0.y, a, c);  split2(v0.z, v0.w, b, d);
    ((uint2*)hi)[base] = make_uint2(a, b);
    ((uint2*)lo)[base] = make_uint2(c, d);
    split2(v1.x, v1.y, a, c);  split2(v1.z, v1.w, b, d);
    ((uint2*)hi)[base + 256] = make_uint2(a, b);
    ((uint2*)lo)[base + 256] = make_uint2(c, d);
    split2(v2.x, v2.y, a, c);  split2(v2.z, v2.w, b, d);
    ((uint2*)hi)[base + 512] = make_uint2(a, b);
    ((uint2*)lo)[base + 512] = make_uint2(c, d);
    split2(v3.x, v3.y, a, c);  split2(v3.z, v3.w, b, d);
    ((uint2*)hi)[base + 768] = make_uint2(a, b);
    ((uint2*)lo)[base + 768] = make_uint2(c, d);
}

// ---------------------------------------------------------------------------
// Conversions with 4x ILP
// ---------------------------------------------------------------------------
__global__ void __launch_bounds__(256)
cvt_w_kernel(const float* w0, const float* w1, const float* w2, const float* w3,
             const float* w4, const float* w5, const float* w6, const float* w7,
             __nv_bfloat16* __restrict__ hi, __nv_bfloat16* __restrict__ lo)
{
    const int wi = blockIdx.x >> 8;
    const int ib = (blockIdx.x & 255) * 1024 + threadIdx.x;
    const float* src;
    switch (wi) {
        case 0: src = w0; break;  case 1: src = w1; break;
        case 2: src = w2; break;  case 3: src = w3; break;
        case 4: src = w4; break;  case 5: src = w5; break;
        case 6: src = w6; break;  default: src = w7; break;
    }
    const size_t off = (size_t)wi * (INNER * INNER / 4);
    cvt4(src, (__nv_bfloat16*)((uint2*)hi + off),
         (__nv_bfloat16*)((uint2*)lo + off), ib);
}

__global__ void __launch_bounds__(256)
cvt_hsenc_kernel(const float* __restrict__ hs, const float* __restrict__ enc,
                 __nv_bfloat16* __restrict__ hs_h, __nv_bfloat16* __restrict__ hs_l,
                 __nv_bfloat16* __restrict__ enc_h, __nv_bfloat16* __restrict__ enc_l)
{
    const int bx = blockIdx.x;
    if (bx < 2048) {
        cvt4(hs, hs_h, hs_l, bx * 1024 + threadIdx.x);
    } else {
        cvt4(enc, enc_h, enc_l, (bx - 2048) * 1024 + threadIdx.x);
    }
}

// ---------------------------------------------------------------------------
// Paired-nbp 3-pass MMA block: acc dependency distance = 8 MMAs.
// ---------------------------------------------------------------------------
#define MMA_BLOCK_PAIR(acc, abaseh, abasel, bbaseh, bbasel, ks)               \
    {                                                                         \
        uint32_t a0h[4], a1h[4], a0l[4], a1l[4];                              \
        ldsm_x4(a0h, (abaseh) + (ks) * 2);                                    \
        ldsm_x4(a1h, (abaseh) + (ks) * 2 + 16 * PADK * 2);                    \
        ldsm_x4(a0l, (abasel) + (ks) * 2);                                    \
        ldsm_x4(a1l, (abasel) + (ks) * 2 + 16 * PADK * 2);                    \
        _Pragma("unroll")                                                     \
        for (int pp = 0; pp < 2; pp++) {                                      \
            const int n0p = pp * 2, n1p = pp * 2 + 1;                         \
            uint32_t b0h[4], b1h[4], b0l[4], b1l[4];                          \
            ldsm_x4(b0h, (bbaseh) + (ks) * 2 + n0p * 16 * PADK * 2);          \
            ldsm_x4(b1h, (bbaseh) + (ks) * 2 + n1p * 16 * PADK * 2);          \
            ldsm_x4(b0l, (bbasel) + (ks) * 2 + n0p * 16 * PADK * 2);          \
            ldsm_x4(b1l, (bbasel) + (ks) * 2 + n1p * 16 * PADK * 2);          \
            /* hh pass (8) */                                                 \
            mma16816(acc[0][2 * n0p],     a0h, b0h);                          \
            mma16816(acc[0][2 * n0p + 1], a0h, b0h + 2);                      \
            mma16816(acc[1][2 * n0p],     a1h, b0h);                          \
            mma16816(acc[1][2 * n0p + 1], a1h, b0h + 2);                      \
            mma16816(acc[0][2 * n1p],     a0h, b1h);                          \
            mma16816(acc[0][2 * n1p + 1], a0h, b1h + 2);                      \
            mma16816(acc[1][2 * n1p],     a1h, b1h);                          \
            mma16816(acc[1][2 * n1p + 1], a1h, b1h + 2);                      \
            /* hl pass (8) */                                                 \
            mma16816(acc[0][2 * n0p],     a0h, b0l);                          \
            mma16816(acc[0][2 * n0p + 1], a0h, b0l + 2);                      \
            mma16816(acc[1][2 * n0p],     a1h, b0l);                          \
            mma16816(acc[1][2 * n0p + 1], a1h, b0l + 2);                      \
            mma16816(acc[0][2 * n1p],     a0h, b1l);                          \
            mma16816(acc[0][2 * n1p + 1], a0h, b1l + 2);                      \
            mma16816(acc[1][2 * n1p],     a1h, b1l);                          \
            mma16816(acc[1][2 * n1p + 1], a1h, b1l + 2);                      \
            /* lh pass (8) */                                                 \
            mma16816(acc[0][2 * n0p],     a0l, b0h);                          \
            mma16816(acc[0][2 * n0p + 1], a0l, b0h + 2);                      \
            mma16816(acc[1][2 * n0p],     a1l, b0h);                          \
            mma16816(acc[1][2 * n0p + 1], a1l, b0h + 2);                      \
            mma16816(acc[0][2 * n1p],     a0l, b1h);                          \
            mma16816(acc[0][2 * n1p + 1], a0l, b1h + 2);                      \
            mma16816(acc[1][2 * n1p],     a1l, b1h);                          \
            mma16816(acc[1][2 * n1p + 1], a1l, b1h + 2);                      \
        }                                                                     \
    }

// ---------------------------------------------------------------------------
// Shared GEMM mainloop (v1): 128x128 CTA, 256 threads, 2 CTAs/SM, 2-stage.
// ---------------------------------------------------------------------------
#define PADK 40
#define GT_TILE  (128 * PADK)
#define GT_STAGE (4 * GT_TILE)
#define GEMM1_SMEM_BYTES (2 * GT_STAGE * 2)

#define GEMM_V1_MAINLOOP(Ah, Al, Wh, Wl, K, acc)                              \
    const int tile = t >> 6;                                                  \
    const int l64  = t & 63;                                                  \
    const int lrr  = l64 >> 2;                                                \
    const int lcc  = (l64 & 3) * 8;                                           \
    const __nv_bfloat16* gsrc =                                               \
        (tile == 0) ? Ah : (tile == 1) ? Al : (tile == 2) ? Wh : Wl;          \
    const int rowbase = (tile < 2) ? m0 : n0;                                 \
    const uint32_t smb = smem_u32(sm);                                        \
    const uint32_t sdst0 = smb + ((tile * GT_TILE + lrr * PADK + lcc) << 1);  \
    const __nv_bfloat16* gp = gsrc + (size_t)(rowbase + lrr) * K + lcc;       \
    const uint32_t abase_rel = (((wm * 32 + (lane & 15)) * PADK +             \
                                 ((lane >> 4) << 3)) << 1);                   \
    const uint32_t bbase_rel = ((2 * GT_TILE +                                \
        (wn * 64 + (lane & 7) + ((lane >> 4) << 3)) * PADK +                  \
        (((lane >> 3) & 1) << 3)) << 1);                                      \
    const int NT = K / 32;                                                    \
    {                                                                         \
        const __nv_bfloat16* g = gp;                                          \
        _Pragma("unroll")                                                     \
        for (int i = 0; i < 8; i++)                                           \
            CP_ASYNC16(sdst0 + (uint32_t)((i * 16 * PADK) << 1),              \
                       g + (size_t)(i * 16) * K);                             \
        CP_COMMIT();                                                          \
    }                                                                         \
    for (int kt = 0; kt < NT; kt++) {                                         \
        const int b = kt & 1;                                                 \
        if (kt + 1 < NT) {                                                    \
            const __nv_bfloat16* g = gp + (kt + 1) * 32;                      \
            const uint32_t d = sdst0 +                                        \
                (uint32_t)((((kt + 1) & 1) * GT_STAGE) << 1);                 \
            _Pragma("unroll")                                                 \
            for (int i = 0; i < 8; i++)                                       \
                CP_ASYNC16(d + (uint32_t)((i * 16 * PADK) << 1),              \
                           g + (size_t)(i * 16) * K);                         \
            CP_COMMIT();                                                      \
            CP_WAIT1();                                                       \
        } else {                                                              \
            CP_WAIT0();                                                       \
        }                                                                     \
        __syncthreads();                                                      \
        const uint32_t stage  = smb + (uint32_t)((b * GT_STAGE) << 1);        \
        const uint32_t abaseh = stage + abase_rel;                            \
        const uint32_t abasel = abaseh + (GT_TILE << 1);                      \
        const uint32_t bbaseh = stage + bbase_rel;                            \
        const uint32_t bbasel = bbaseh + (GT_TILE << 1);                      \
        _Pragma("unroll")                                                     \
        for (int ks = 0; ks < 32; ks += 16) {                                 \
            MMA_BLOCK_PAIR(acc, abaseh, abasel, bbaseh, bbasel, ks)           \
        }                                                                     \
        __syncthreads();                                                      \
    }

// ---------------------------------------------------------------------------
// Generic v1 GEMM (fp32 C + optional bias)
// ---------------------------------------------------------------------------
__global__ void __launch_bounds__(256, 2)
gemm_bf3_kernel(const __nv_bfloat16* __restrict__ Ah, const __nv_bfloat16* __restrict__ Al,
                const __nv_bfloat16* __restrict__ Wh, const __nv_bfloat16* __restrict__ Wl,
                const float* __restrict__ bias, float* __restrict__ C,
                int M, int N, int K)
{
    extern __shared__ __nv_bfloat16 sm[];
    const int t    = threadIdx.x;
    const int lane = t & 31;
    const int wid  = t >> 5;
    const int wm   = wid >> 1;
    const int wn   = wid & 1;
    const int m0   = blockIdx.y * 128;
    const int n0   = blockIdx.x * 128;

    float acc[2][8][4];
#pragma unroll
    for (int i = 0; i < 2; i++)
#pragma unroll
        for (int j = 0; j < 8; j++)
#pragma unroll
            for (int q = 0; q < 4; q++) acc[i][j][q] = 0.f;

    GEMM_V1_MAINLOOP(Ah, Al, Wh, Wl, K, acc)

    const int r0 = m0 + wm * 32 + (lane >> 2);
    const int c0 = n0 + wn * 64 + (lane & 3) * 2;
#pragma unroll
    for (int mi = 0; mi < 2; mi++) {
        const int r = r0 + mi * 16;
#pragma unroll
        for (int nb = 0; nb < 8; nb++) {
            const int c = c0 + nb * 8;
            float b0 = 0.f, b1 = 0.f;
            if (bias) { b0 = bias[c]; b1 = bias[c + 1]; }
            *(float2*)(C + (size_t)r * N + c) =
                make_float2(acc[mi][nb][0] + b0, acc[mi][nb][1] + b1);
            *(float2*)(C + (size_t)(r + 8) * N + c) =
                make_float2(acc[mi][nb][2] + b0, acc[mi][nb][3] + b1);
        }
    }
}

// ---------------------------------------------------------------------------
// Fused QKV GEMM (RMSNorm + RoPE + scatter epilogue)
// ---------------------------------------------------------------------------
__global__ void __launch_bounds__(256, 2)
gemm_qkv_fused_kernel(const __nv_bfloat16* __restrict__ Ah, const __nv_bfloat16* __restrict__ Al,
                      const __nv_bfloat16* __restrict__ Wh, const __nv_bfloat16* __restrict__ Wl,
                      const float* __restrict__ gq, const float* __restrict__ gk,
                      const float* __restrict__ cosb, const float* __restrict__ sinb,
                      __nv_bfloat16* __restrict__ QAh, __nv_bfloat16* __restrict__ QAl,
                      __nv_bfloat16* __restrict__ KAh, __nv_bfloat16* __restrict__ KAl,
                      __nv_bfloat16* __restrict__ VAh, __nv_bfloat16* __restrict__ VAl)
{
    extern __shared__ __nv_bfloat16 sm[];
    const int t    = threadIdx.x;
    const int lane = t & 31;
    const int wid  = t >> 5;
    const int wm   = wid >> 1;
    const int wn   = wid & 1;
    const int m0   = blockIdx.y * 128;
    const int n0   = blockIdx.x * 128;
    const int K    = INNER;

    float acc[2][8][4];
#pragma unroll
    for (int i = 0; i < 2; i++)
#pragma unroll
        for (int j = 0; j < 8; j++)
#pragma unroll
            for (int q = 0; q < 4; q++) acc[i][j][q] = 0.f;

    GEMM_V1_MAINLOOP(Ah, Al, Wh, Wl, K, acc)

    const int nhead = (n0 >> 6) + wn;
    const int sec   = nhead >> 4;
    const int hh    = nhead & 15;
    const int dq    = (lane & 3) * 2;
    const int rbase = m0 + wm * 32 + (lane >> 2);

    __nv_bfloat16* outh = (sec == 0) ? QAh : (sec == 1) ? KAh : VAh;
    __nv_bfloat16* outl = (sec == 0) ? QAl : (sec == 1) ? KAl : VAl;
    const float* gvec = (sec == 0) ? gq : gk;
    const float qscale = (sec == 0) ? ATTN_SCALE : 1.0f;

#pragma unroll
    for (int mi = 0; mi < 2; mi++) {
#pragma unroll
        for (int half = 0; half < 2; half++) {
            const int row = rbase + mi * 16 + half * 8;
            const int vi = half * 2;
            const int j = row & 7, tt = row >> 3;
            const size_t dstb = (((size_t)(j * NUM_HEADS + hh)) * STOT + tt) * HEAD_DIM;
            uint32_t* oh32 = (uint32_t*)(outh + dstb);
            uint32_t* ol32 = (uint32_t*)(outl + dstb);

            if (sec == 2) {
#pragma unroll
                for (int nb = 0; nb < 8; nb++) {
                    uint32_t hi, lo;
                    split2(acc[mi][nb][vi], acc[mi][nb][vi + 1], hi, lo);
                    const int d = dq + nb * 8;
                    oh32[d >> 1] = hi;
                    ol32[d >> 1] = lo;
                }
            } else {
                float ss = 0.f;
#pragma unroll
                for (int nb = 0; nb < 8; nb++) {
                    ss += acc[mi][nb][vi] * acc[mi][nb][vi];
                    ss += acc[mi][nb][vi + 1] * acc[mi][nb][vi + 1];
                }
                ss += __shfl_xor_sync(0xffffffffu, ss, 1);
                ss += __shfl_xor_sync(0xffffffffu, ss, 2);
                const float rms = rsqrtf(ss * (1.f / HEAD_DIM) + EPS_RMS);

                const float* cb = cosb + (size_t)row * HEAD_DIM;
                const float* sb = sinb + (size_t)row * HEAD_DIM;
#pragma unroll
                for (int nb = 0; nb < 4; nb++) {
                    const int d0 = dq + nb * 8;
                    const int d1 = d0 + 32;
                    const float x00 = acc[mi][nb][vi]         * rms * gvec[d0];
                    const float x01 = acc[mi][nb][vi + 1]     * rms * gvec[d0 + 1];
                    const float x10 = acc[mi][nb + 4][vi]     * rms * gvec[d1];
                    const float x11 = acc[mi][nb + 4][vi + 1] * rms * gvec[d1 + 1];
                    const float y00 = (x00 * cb[d0]     - x10 * sb[d0])     * qscale;
                    const float y01 = (x01 * cb[d0 + 1] - x11 * sb[d0 + 1]) * qscale;
                    const float y10 = (x10 * cb[d1]     + x00 * sb[d1])     * qscale;
                    const float y11 = (x11 * cb[d1 + 1] + x01 * sb[d1 + 1]) * qscale;
                    uint32_t hi, lo;
                    split2(y00, y01, hi, lo);
                    oh32[d0 >> 1] = hi;
                    ol32[d0 >> 1] = lo;
                    split2(y10, y11, hi, lo);
                    oh32[d1 >> 1] = hi;
                    ol32[d1 >> 1] = lo;
                }
            }
        }
    }
}

// ---------------------------------------------------------------------------
// GEMM v2: 256x128 CTA, 512 threads, 3-stage, K-split (small-M GEMMs)
// ---------------------------------------------------------------------------
#define V2_TILE_A (256 * PADK)
#define V2_TILE_W (128 * PADK)
#define V2_STAGE (2 * V2_TILE_A + 2 * V2_TILE_W)
#define GEMM2_SMEM_BYTES (3 * V2_STAGE * 2)

__global__ void __launch_bounds__(512, 1)
gemm_v2_kernel(const __nv_bfloat16* __restrict__ Ah, const __nv_bfloat16* __restrict__ Al,
               const __nv_bfloat16* __restrict__ Wh, const __nv_bfloat16* __restrict__ Wl,
               float* __restrict__ C, int M, int N, int K, int kparts)
{
    extern __shared__ __nv_bfloat16 sm[];
    const int t    = threadIdx.x;
    const int lane = t & 31;
    const int wid  = t >> 5;
    const int wm   = wid >> 1;
    const int wn   = wid & 1;
    const int m0   = blockIdx.y * 256;
    const int n0   = blockIdx.x * 128;

    const int KC    = K / kparts;
    const int kbase = blockIdx.z * KC;
    const int NT    = KC / 32;

    float acc[2][8][4];
#pragma unroll
    for (int i = 0; i < 2; i++)
#pragma unroll
        for (int j = 0; j < 8; j++)
#pragma unroll
            for (int q = 0; q < 4; q++) acc[i][j][q] = 0.f;

    const int rr = t >> 2;
    const int cc = (t & 3) * 8;
    const uint32_t smb = smem_u32(sm);

    const __nv_bfloat16* pA0 = Ah + (size_t)(m0 + rr)       * K + kbase + cc;
    const __nv_bfloat16* pA1 = Ah + (size_t)(m0 + rr + 128) * K + kbase + cc;
    const __nv_bfloat16* pL0 = Al + (size_t)(m0 + rr)       * K + kbase + cc;
    const __nv_bfloat16* pL1 = Al + (size_t)(m0 + rr + 128) * K + kbase + cc;
    const __nv_bfloat16* pWh = Wh + (size_t)(n0 + rr)       * K + kbase + cc;
    const __nv_bfloat16* pWl = Wl + (size_t)(n0 + rr)       * K + kbase + cc;

    const uint32_t dA0 = (uint32_t)((rr * PADK + cc) << 1);
    const uint32_t dA1 = (uint32_t)(((rr + 128) * PADK + cc) << 1);
    const uint32_t dL0 = dA0 + (uint32_t)(V2_TILE_A << 1);
    const uint32_t dL1 = dA1 + (uint32_t)(V2_TILE_A << 1);
    const uint32_t dWh = dA0 + (uint32_t)((2 * V2_TILE_A) << 1);
    const uint32_t dWl = dA0 + (uint32_t)(((2 * V2_TILE_A) + V2_TILE_W) << 1);

#define V2_LOAD(kt, stg) do {                                              \
    const uint32_t sb = smb + (uint32_t)(((stg) * V2_STAGE) << 1);         \
    const int ko = (kt) * 32;                                              \
    CP_ASYNC16(sb + dA0, pA0 + ko);                                        \
    CP_ASYNC16(sb + dA1, pA1 + ko);                                        \
    CP_ASYNC16(sb + dL0, pL0 + ko);                                        \
    CP_ASYNC16(sb + dL1, pL1 + ko);                                        \
    CP_ASYNC16(sb + dWh, pWh + ko);                                        \
    CP_ASYNC16(sb + dWl, pWl + ko);                                        \
    CP_COMMIT();                                                           \
} while (0)

    V2_LOAD(0, 0);
    V2_LOAD(1, 1);

    const uint32_t abase_rel = (uint32_t)((((wm * 32 + (lane & 15)) * PADK +
                                            ((lane >> 4) << 3))) << 1);
    const uint32_t bbase_rel = (uint32_t)(((2 * V2_TILE_A +
                     (wn * 64 + (lane & 7) + ((lane >> 4) << 3)) * PADK +
                     (((lane >> 3) & 1) << 3))) << 1);

    int stg = 0;
    for (int kt = 0; kt < NT; kt++) {
        if (kt + 2 < NT) {
            const int ps = (stg + 2 >= 3) ? (stg - 1) : (stg + 2);
            V2_LOAD(kt + 2, ps);
            CP_WAIT2();
        } else {
            CP_WAIT0();
        }
        __syncthreads();

        const uint32_t stage  = smb + (uint32_t)((stg * V2_STAGE) << 1);
        const uint32_t abaseh = stage + abase_rel;
        const uint32_t abasel = abaseh + (uint32_t)(V2_TILE_A << 1);
        const uint32_t bbaseh = stage + bbase_rel;
        const uint32_t bbasel = bbaseh + (uint32_t)(V2_TILE_W << 1);

#pragma unroll
        for (int ks = 0; ks < 32; ks += 16) {
            MMA_BLOCK_PAIR(acc, abaseh, abasel, bbaseh, bbasel, ks)
        }
        __syncthreads();
        stg = (stg + 1 >= 3) ? 0 : (stg + 1);
    }

    float* Cz = C + (size_t)blockIdx.z * M * N;
    const int r0 = m0 + wm * 32 + (lane >> 2);
    const int c0 = n0 + wn * 64 + (lane & 3) * 2;
#pragma unroll
    for (int mi = 0; mi < 2; mi++) {
        const int r = r0 + mi * 16;
#pragma unroll
        for (int nb = 0; nb < 8; nb++) {
            const int c = c0 + nb * 8;
            *(float2*)(Cz + (size_t)r * N + c) =
                make_float2(acc[mi][nb][0], acc[mi][nb][1]);
            *(float2*)(Cz + (size_t)(r + 8) * N + c) =
                make_float2(acc[mi][nb][2], acc[mi][nb][3]);
        }
    }
}

// ---------------------------------------------------------------------------
// K-split reduce (with bias)
// ---------------------------------------------------------------------------
__global__ void __launch_bounds__(256)
reduce4_kernel(const float* __restrict__ part, const float* __restrict__ bias,
               float* __restrict__ out, int MN, int N)
{
    const int i = blockIdx.x * 256 + threadIdx.x;
    if (i * 4 >= MN) return;
    const int q = MN / 4;
    float4 a = ((const float4*)part)[i];
    float4 b = ((const float4*)part)[i + q];
    float4 c = ((const float4*)part)[i + 2 * q];
    float4 d = ((const float4*)part)[i + 3 * q];
    float4 r = make_float4(a.x + b.x + c.x + d.x, a.y + b.y + c.y + d.y,
                           a.z + b.z + c.z + d.z, a.w + b.w + c.w + d.w);
    if (bias) {
        const int col = (i * 4) % N;
        r.x += bias[col];  r.y += bias[col + 1];
        r.z += bias[col + 2];  r.w += bias[col + 3];
    }
    ((float4*)out)[i] = r;
}

// ---------------------------------------------------------------------------
// RMSNorm + broadcast scatter (text), reads 4 K-split partials directly
// ---------------------------------------------------------------------------
__global__ void __launch_bounds__(256)
enc_post_kernel(const float* __restrict__ part,
                const float* __restrict__ gaq, const float* __restrict__ gak,
                __nv_bfloat16* __restrict__ QAh, __nv_bfloat16* __restrict__ QAl,
                __nv_bfloat16* __restrict__ KAh, __nv_bfloat16* __restrict__ KAl,
                __nv_bfloat16* __restrict__ VAh, __nv_bfloat16* __restrict__ VAl)
{
    const int warp = (blockIdx.x * blockDim.x + threadIdx.x) >> 5;
    const int lane = threadIdx.x & 31;
    const int tt = warp >> 4;
    const int h  = warp & 15;
    if (tt >= T_LEN) return;

    const size_t src = (size_t)tt * INNER3 + h * HEAD_DIM;
    const size_t PQ = (size_t)T_LEN * INNER3;
    float a0 = 0.f, a1 = 0.f, b0 = 0.f, b1 = 0.f, v0 = 0.f, v1 = 0.f;
#pragma unroll
    for (int z = 0; z < 4; z++) {
        const float* p = part + z * PQ + src;
        a0 += p[lane];              a1 += p[lane + 32];
        b0 += p[INNER + lane];      b1 += p[INNER + lane + 32];
        v0 += p[2*INNER + lane];    v1 += p[2*INNER + lane + 32];
    }

    float ra = rsqrtf(warp_sum32(a0 * a0 + a1 * a1) * (1.f / HEAD_DIM) + EPS_RMS);
    float rb = rsqrtf(warp_sum32(b0 * b0 + b1 * b1) * (1.f / HEAD_DIM) + EPS_RMS);

    a0 *= ra * gaq[lane] * ATTN_SCALE;  a1 *= ra * gaq[lane + 32] * ATTN_SCALE;
    b0 *= rb * gak[lane];               b1 *= rb * gak[lane + 32];

#pragma unroll
    for (int j = 0; j < SPARSE_N; j++) {
        const size_t dst =
            (((size_t)(j * NUM_HEADS + h)) * STOT + G_LEN + tt) * HEAD_DIM;
        store_split(QAh, QAl, dst + lane,      a0);
        store_split(QAh, QAl, dst + lane + 32, a1);
        store_split(KAh, KAl, dst + lane,      b0);
        store_split(KAh, KAl, dst + lane + 32, b1);
        store_split(VAh, VAl, dst + lane,      v0);
        store_split(VAh, VAl, dst + lane + 32, v1);
    }
}

// ---------------------------------------------------------------------------
// Flash attention, BQ=256, 512 threads, static-max softmax, fused vis gather,
// paired-nbp MMA ordering.
// ---------------------------------------------------------------------------
#define APAD 72
#define AQ_ELEMS (2 * 256 * APAD)
#define KV_TILE  (64 * APAD)
#define KV_STAGE (4 * KV_TILE)
#define ATT_SM_BYTES ((AQ_ELEMS + 2 * KV_STAGE) * 2)

__global__ void __launch_bounds__(512, 1)
attn_mma_kernel(const __nv_bfloat16* __restrict__ Qhg, const __nv_bfloat16* __restrict__ Qlg,
                const __nv_bfloat16* __restrict__ Khg, const __nv_bfloat16* __restrict__ Klg,
                const __nv_bfloat16* __restrict__ Vhg, const __nv_bfloat16* __restrict__ Vlg,
                float* __restrict__ OA,
                __nv_bfloat16* __restrict__ vis_h, __nv_bfloat16* __restrict__ vis_l)
{
    extern __shared__ __nv_bfloat16 smA[];
    const int t    = threadIdx.x;
    const int lane = t & 31;
    const int w    = t >> 5;
    const int jh   = blockIdx.y;
    const int q0   = blockIdx.x * 256;
    const size_t base = (size_t)jh * STOT * HEAD_DIM;

    const uint32_t smb = smem_u32(smA);

    const int tile = t >> 7;
    const int l128 = t & 127;
    const int krr  = l128 >> 3;
    const int kcc  = (l128 & 7) * 8;
    const __nv_bfloat16* kvsrc =
        (tile == 0) ? Khg : (tile == 1) ? Klg : (tile == 2) ? Vhg : Vlg;
    const uint32_t kvdst0 = smb + ((AQ_ELEMS + tile * KV_TILE + krr * APAD + kcc) << 1);

    {
        const __nv_bfloat16* g = kvsrc + base + (size_t)krr * 64 + kcc;
#pragma unroll
        for (int i = 0; i < 4; i++)
            CP_ASYNC16(kvdst0 + (uint32_t)((i * 16 * APAD) << 1),
                       g + (size_t)(i * 16) * 64);
        CP_COMMIT();
    }

    {
        const int row = t >> 1, c0 = (t & 1) * 32;
        const __nv_bfloat16* gh = Qhg + base + (size_t)(q0 + row) * 64 + c0;
        const __nv_bfloat16* gl = Qlg + base + (size_t)(q0 + row) * 64 + c0;
        __nv_bfloat16* sh = smA + row * APAD + c0;
        __nv_bfloat16* sl = smA + 256 * APAD + row * APAD + c0;
#pragma unroll
        for (int c = 0; c < 32; c += 8) {
            *(uint4*)(sh + c) = *(const uint4*)(gh + c);
            *(uint4*)(sl + c) = *(const uint4*)(gl + c);
        }
    }

    float o[8][4];
#pragma unroll
    for (int i = 0; i < 8; i++)
#pragma unroll
        for (int j = 0; j < 4; j++) o[i][j] = 0.f;
    float l0r = 0.f, l1r = 0.f;

    const uint32_t qfragh = smb + (((w * 16 + (lane & 15)) * APAD + ((lane >> 4) << 3)) << 1);
    const uint32_t qfragl = qfragh + ((256 * APAD) << 1);
    const uint32_t kfrag_rel = ((((lane & 7) + ((lane >> 4) << 3)) * APAD + (((lane >> 3) & 1) << 3)) << 1);
    const uint32_t vfrag_rel = (((2 * KV_TILE) + ((lane & 7) + (((lane >> 3) & 1) << 3)) * APAD + ((lane >> 4) << 3)) << 1);

    for (int kt = 0; kt < 20; kt++) {
        const int b = kt & 1;
        if (kt + 1 < 20) {
            const __nv_bfloat16* g = kvsrc + base + (size_t)((kt + 1) * 64 + krr) * 64 + kcc;
            const uint32_t d = kvdst0 + (uint32_t)((((kt + 1) & 1) * KV_STAGE) << 1);
#pragma unroll
            for (int i = 0; i < 4; i++)
                CP_ASYNC16(d + (uint32_t)((i * 16 * APAD) << 1),
                           g + (size_t)(i * 16) * 64);
            CP_COMMIT();
            CP_WAIT1();
        } else {
            CP_WAIT0();
        }
        __syncthreads();

        const uint32_t kvstage = smb + (uint32_t)(((AQ_ELEMS + b * KV_STAGE)) << 1);
        const uint32_t kfragh = kvstage + kfrag_rel;
        const uint32_t kfragl = kfragh + (KV_TILE << 1);
        const uint32_t vfrag  = kvstage + vfrag_rel;

        float s[8][4];
#pragma unroll
        for (int i = 0; i < 8; i++)
#pragma unroll
            for (int j = 0; j < 4; j++) s[i][j] = 0.f;

        // ---- scores (paired-nbp, 3-pass) ----
#pragma unroll
        for (int ks = 0; ks < 64; ks += 16) {
            uint32_t ah[4], al[4];
            ldsm_x4(ah, qfragh + ks * 2);
            ldsm_x4(al, qfragl + ks * 2);
#pragma unroll
            for (int pp = 0; pp < 2; pp++) {
                const int n0p = pp * 2, n1p = pp * 2 + 1;
                uint32_t k0h[4], k1h[4], k0l[4], k1l[4];
                ldsm_x4(k0h, kfragh + ks * 2 + n0p * 16 * APAD * 2);
                ldsm_x4(k1h, kfragh + ks * 2 + n1p * 16 * APAD * 2);
                ldsm_x4(k0l, kfragl + ks * 2 + n0p * 16 * APAD * 2);
                ldsm_x4(k1l, kfragl + ks * 2 + n1p * 16 * APAD * 2);
                mma16816(s[2 * n0p],     ah, k0h);
                mma16816(s[2 * n0p + 1], ah, k0h + 2);
                mma16816(s[2 * n1p],     ah, k1h);
                mma16816(s[2 * n1p + 1], ah, k1h + 2);
                mma16816(s[2 * n0p],     ah, k0l);
                mma16816(s[2 * n0p + 1], ah, k0l + 2);
                mma16816(s[2 * n1p],     ah, k1l);
                mma16816(s[2 * n1p + 1], ah, k1l + 2);
                mma16816(s[2 * n0p],     al, k0h);
                mma16816(s[2 * n0p + 1], al, k0h + 2);
                mma16816(s[2 * n1p],     al, k1h);
                mma16816(s[2 * n1p + 1], al, k1h + 2);
            }
        }

        // ---- static-max softmax ----
        float rs0 = 0.f, rs1 = 0.f;
#pragma unroll
        for (int nb = 0; nb < 8; nb++) {
            s[nb][0] = __expf(s[nb][0] - SMAX);  rs0 += s[nb][0];
            s[nb][1] = __expf(s[nb][1] - SMAX);  rs0 += s[nb][1];
            s[nb][2] = __expf(s[nb][2] - SMAX);  rs1 += s[nb][2];
            s[nb][3] = __expf(s[nb][3] - SMAX);  rs1 += s[nb][3];
        }
        rs0 += __shfl_xor_sync(0xffffffffu, rs0, 1);
        rs0 += __shfl_xor_sync(0xffffffffu, rs0, 2);
        rs1 += __shfl_xor_sync(0xffffffffu, rs1, 1);
        rs1 += __shfl_xor_sync(0xffffffffu, rs1, 2);
        l0r += rs0;
        l1r += rs1;

        // ---- PV (paired-dbp, 3-pass) ----
#pragma unroll
        for (int kb2 = 0; kb2 < 4; kb2++) {
            uint32_t ph[4], pl[4];
            split2(s[2 * kb2][0],     s[2 * kb2][1],     ph[0], pl[0]);
            split2(s[2 * kb2][2],     s[2 * kb2][3],     ph[1], pl[1]);
            split2(s[2 * kb2 + 1][0], s[2 * kb2 + 1][1], ph[2], pl[2]);
            split2(s[2 * kb2 + 1][2], s[2 * kb2 + 1][3], ph[3], pl[3]);
            const uint32_t vb = vfrag + kb2 * 16 * APAD * 2;
#pragma unroll
            for (int pp = 0; pp < 2; pp++) {
                const int d0p = pp * 2, d1p = pp * 2 + 1;
                uint32_t v0h[4], v1h[4], v0l[4], v1l[4];
                ldsm_x4_t(v0h, vb + d0p * 16 * 2);
                ldsm_x4_t(v1h, vb + d1p * 16 * 2);
                ldsm_x4_t(v0l, vb + (KV_TILE << 1) + d0p * 16 * 2);
                ldsm_x4_t(v1l, vb + (KV_TILE << 1) + d1p * 16 * 2);
                mma16816(o[2 * d0p],     ph, v0h);
                mma16816(o[2 * d0p + 1], ph, v0h + 2);
                mma16816(o[2 * d1p],     ph, v1h);
                mma16816(o[2 * d1p + 1], ph, v1h + 2);
                mma16816(o[2 * d0p],     ph, v0l);
                mma16816(o[2 * d0p + 1], ph, v0l + 2);
                mma16816(o[2 * d1p],     ph, v1l);
                mma16816(o[2 * d1p + 1], ph, v1l + 2);
                mma16816(o[2 * d0p],     pl, v0h);
                mma16816(o[2 * d0p + 1], pl, v0h + 2);
                mma16816(o[2 * d1p],     pl, v1h);
                mma16816(o[2 * d1p + 1], pl, v1h + 2);
            }
        }
        __syncthreads();
    }

    const float inv0 = 1.f / l0r, inv1 = 1.f / l1r;
    const int row = q0 + w * 16 + (lane >> 2);
    const int col = (lane & 3) * 2;
    if (blockIdx.x < 4) {
        const int j = jh >> 4, h = jh & 15;
        uint32_t* vh32 = (uint32_t*)vis_h;
        uint32_t* vl32 = (uint32_t*)vis_l;
        const size_t b0 = ((size_t)row * 8 + j) * INNER + h * 64;
        const size_t b1 = ((size_t)(row + 8) * 8 + j) * INNER + h * 64;
#pragma unroll
        for (int db = 0; db < 8; db++) {
            uint32_t hi, lo;
            split2(o[db][0] * inv0, o[db][1] * inv0, hi, lo);
            vh32[(b0 + db * 8 + col) >> 1] = hi;
            vl32[(b0 + db * 8 + col) >> 1] = lo;
            split2(o[db][2] * inv1, o[db][3] * inv1, hi, lo);
            vh32[(b1 + db * 8 + col) >> 1] = hi;
            vl32[(b1 + db * 8 + col) >> 1] = lo;
        }
    } else {
#pragma unroll
        for (int db = 0; db < 8; db++) {
            *(float2*)(OA + base + (size_t)row * 64 + db * 8 + col) =
                make_float2(o[db][0] * inv0, o[db][1] * inv0);
            *(float2*)(OA + base + (size_t)(row + 8) * 64 + db * 8 + col) =
                make_float2(o[db][2] * inv1, o[db][3] * inv1);
        }
    }
}

// ---------------------------------------------------------------------------
// Gather text rows -> bf16 hi/lo (mean over j)
// ---------------------------------------------------------------------------
__global__ void __launch_bounds__(256)
gather_txt_kernel(const float* __restrict__ OA,
                  __nv_bfloat16* __restrict__ th, __nv_bfloat16* __restrict__ tl)
{
    const int i = blockIdx.x * 256 + threadIdx.x;
    const int idx = i * 4;
    const int tt = idx >> 10, e = idx & 1023;
    const int h = e >> 6, d = e & 63;
    float4 acc = make_float4(0.f, 0.f, 0.f, 0.f);
#pragma unroll
    for (int j = 0; j < SPARSE_N; j++) {
        float4 v = *(const float4*)(OA +
            (((size_t)(j * NUM_HEADS + h)) * STOT + G_LEN + tt) * HEAD_DIM + d);
        acc.x += v.x; acc.y += v.y; acc.z += v.z; acc.w += v.w;
    }
    acc.x *= 0.125f; acc.y *= 0.125f; acc.z *= 0.125f; acc.w *= 0.125f;
    uint32_t h01, l01, h23, l23;
    split2(acc.x, acc.y, h01, l01);
    split2(acc.z, acc.w, h23, l23);
    ((uint2*)th)[i] = make_uint2(h01, h23);
    ((uint2*)tl)[i] = make_uint2(l01, l23);
}

// ---------------------------------------------------------------------------
// kernel_launch
// ---------------------------------------------------------------------------
extern "C" void kernel_launch(void* const* d_in, const int* in_sizes, int n_in,
                              void* d_out, int out_size)
{
    const float* hs   = (const float*)d_in[0];
    const float* enc  = (const float*)d_in[1];
    const float* bout  = (const float*)d_in[9];
    const float* baout = (const float*)d_in[11];
    const float* gq   = (const float*)d_in[12];
    const float* gk   = (const float*)d_in[13];
    const float* gaq  = (const float*)d_in[14];
    const float* gak  = (const float*)d_in[15];
    const float* rc   = (const float*)d_in[16];
    const float* rs   = (const float*)d_in[17];
    float* out = (float*)d_out;

    float *encpart, *txtpart, *OA;
    __nv_bfloat16 *hs_h, *hs_l, *enc_h, *enc_l, *w_h, *w_l;
    __nv_bfloat16 *vis_h, *vis_l, *txt_h, *txt_l;
    __nv_bfloat16 *QAh, *QAl, *KAh, *KAl, *VAh, *VAl;
    cudaGetSymbolAddress((void**)&encpart, g_encpart);
    cudaGetSymbolAddress((void**)&txtpart, g_txtpart);
    cudaGetSymbolAddress((void**)&OA,    g_OA);
    cudaGetSymbolAddress((void**)&hs_h,  g_hs_h);
    cudaGetSymbolAddress((void**)&hs_l,  g_hs_l);
    cudaGetSymbolAddress((void**)&enc_h, g_enc_h);
    cudaGetSymbolAddress((void**)&enc_l, g_enc_l);
    cudaGetSymbolAddress((void**)&w_h,   g_w_h);
    cudaGetSymbolAddress((void**)&w_l,   g_w_l);
    cudaGetSymbolAddress((void**)&vis_h, g_vis_h);
    cudaGetSymbolAddress((void**)&vis_l, g_vis_l);
    cudaGetSymbolAddress((void**)&txt_h, g_txt_h);
    cudaGetSymbolAddress((void**)&txt_l, g_txt_l);
    cudaGetSymbolAddress((void**)&QAh,   g_QAh);
    cudaGetSymbolAddress((void**)&QAl,   g_QAl);
    cudaGetSymbolAddress((void**)&KAh,   g_KAh);
    cudaGetSymbolAddress((void**)&KAl,   g_KAl);
    cudaGetSymbolAddress((void**)&VAh,   g_VAh);
    cudaGetSymbolAddress((void**)&VAl,   g_VAl);

    cudaFuncSetAttribute(gemm_bf3_kernel,
                         cudaFuncAttributeMaxDynamicSharedMemorySize, GEMM1_SMEM_BYTES);
    cudaFuncSetAttribute(gemm_qkv_fused_kernel,
                         cudaFuncAttributeMaxDynamicSharedMemorySize, GEMM1_SMEM_BYTES);
    cudaFuncSetAttribute(gemm_v2_kernel,
                         cudaFuncAttributeMaxDynamicSharedMemorySize, GEMM2_SMEM_BYTES);
    cudaFuncSetAttribute(attn_mma_kernel,
                         cudaFuncAttributeMaxDynamicSharedMemorySize, ATT_SM_BYTES);

    const size_t WS = (size_t)INNER * INNER;

    // [0] weight conversions, [1] hs+enc conversions
    cvt_w_kernel<<<2048, 256>>>(
        (const float*)d_in[2], (const float*)d_in[3], (const float*)d_in[4],
        (const float*)d_in[5], (const float*)d_in[6], (const float*)d_in[7],
        (const float*)d_in[8], (const float*)d_in[10], w_h, w_l);
    cvt_hsenc_kernel<<<2112, 256>>>(hs, enc, hs_h, hs_l, enc_h, enc_l);

    // [2] enc QKV GEMM (v2, K-split x4), [3] enc post (fused reduce)
    gemm_v2_kernel<<<dim3(INNER3 / 128, 1, 4), 512, GEMM2_SMEM_BYTES>>>(
        enc_h, enc_l, w_h + 3 * WS, w_l + 3 * WS, encpart, T_LEN, INNER3, INNER, 4);
    enc_post_kernel<<<(T_LEN * NUM_HEADS) / 8, 256>>>(
        encpart, gaq, gak, QAh, QAl, KAh, KAl, VAh, VAl);

    // [4] big QKV GEMM (fused epilogue)
    gemm_qkv_fused_kernel<<<dim3(INNER3 / 128, S_LEN / 128), 256, GEMM1_SMEM_BYTES>>>(
        hs_h, hs_l, w_h + 0 * WS, w_l + 0 * WS,
        gq, gk, rc, rs, QAh, QAl, KAh, KAl, VAh, VAl);

    // [5] attention
    attn_mma_kernel<<<dim3(STOT / 256, NJH), 512, ATT_SM_BYTES>>>(
        QAh, QAl, KAh, KAl, VAh, VAl, OA, vis_h, vis_l);

    // [6] text gather
    gather_txt_kernel<<<(T_LEN * INNER / 4) / 256, 256>>>(OA, txt_h, txt_l);

    // [7] vis out GEMM (v1, bias)
    gemm_bf3_kernel<<<dim3(INNER / 128, S_LEN / 128), 256, GEMM1_SMEM_BYTES>>>(
        vis_h, vis_l, w_h + 6 * WS, w_l + 6 * WS, bout, out, S_LEN, INNER, INNER);

    // [8] txt out GEMM (v2, K-split x4), [9] reduce with bias
    gemm_v2_kernel<<<dim3(INNER / 128, 1, 4), 512, GEMM2_SMEM_BYTES>>>(
        txt_h, txt_l, w_h + 7 * WS, w_l + 7 * WS, txtpart, T_LEN, INNER, INNER, 4);
    reduce4_kernel<<<(T_LEN * INNER / 4) / 256, 256>>>(
        txtpart, baout, out + (size_t)S_LEN * INNER, T_LEN * INNER, INNER);
}

// round 13
// speedup vs baseline: 1.2357x; 1.2357x over previous
#include <cuda_runtime.h>
#include <cuda_fp16.h>
#include <math.h>
#include <stdint.h>

// ---------------------------------------------------------------------------
// Problem constants
// ---------------------------------------------------------------------------
#define S_LEN     8192
#define T_LEN     256
#define NUM_HEADS 16
#define HEAD_DIM  64
#define INNER     1024
#define INNER3    3072
#define SPARSE_N  8
#define G_LEN     1024
#define STOT      1280
#define NJH       128
#define EPS_RMS   1e-5f
#define ATTN_SCALE 0.125f
#define SMAX      8.0f
#define ATT_ELEMS (NJH * STOT * HEAD_DIM)

// ---------------------------------------------------------------------------
// Static device scratch (fp16 hi/lo where needed; A-side single precision)
// ---------------------------------------------------------------------------
__device__ float g_encpart[4 * T_LEN * INNER3];
__device__ float g_txtpart[4 * T_LEN * INNER];
__device__ float g_OA[ATT_ELEMS];

__device__ __half g_hs_h[S_LEN * INNER];
__device__ __half g_enc_h[T_LEN * INNER];
__device__ __half g_enc_l[T_LEN * INNER];
__device__ __half g_w_h[8 * INNER * INNER];
__device__ __half g_w_l[8 * INNER * INNER];
__device__ __half g_vis_h[S_LEN * INNER];
__device__ __half g_vis_l[S_LEN * INNER];
__device__ __half g_txt_h[T_LEN * INNER];
__device__ __half g_txt_l[T_LEN * INNER];
__device__ __half g_QAh[ATT_ELEMS];
__device__ __half g_KAh[ATT_ELEMS];
__device__ __half g_KAl[ATT_ELEMS];
__device__ __half g_VAh[ATT_ELEMS];
__device__ __half g_VAl[ATT_ELEMS];

// ---------------------------------------------------------------------------
// Helpers
// ---------------------------------------------------------------------------
__device__ __forceinline__ uint32_t smem_u32(const void* p) {
    uint32_t a;
    asm("{ .reg .u64 t; cvta.to.shared.u64 t, %1; cvt.u32.u64 %0, t; }"
        : "=r"(a) : "l"(p));
    return a;
}

#define CP_ASYNC16(dst, src) \
    asm volatile("cp.async.cg.shared.global [%0], [%1], 16;" :: "r"(dst), "l"(src))
#define CP_COMMIT() asm volatile("cp.async.commit_group;" ::: "memory")
#define CP_WAIT0()  asm volatile("cp.async.wait_group 0;" ::: "memory")
#define CP_WAIT1()  asm volatile("cp.async.wait_group 1;" ::: "memory")
#define CP_WAIT2()  asm volatile("cp.async.wait_group 2;" ::: "memory")

__device__ __forceinline__ void ldsm_x4(uint32_t* r, uint32_t a) {
    asm volatile("ldmatrix.sync.aligned.m8n8.x4.shared.b16 {%0,%1,%2,%3}, [%4];"
        : "=r"(r[0]), "=r"(r[1]), "=r"(r[2]), "=r"(r[3]) : "r"(a));
}
__device__ __forceinline__ void ldsm_x4_t(uint32_t* r, uint32_t a) {
    asm volatile("ldmatrix.sync.aligned.m8n8.x4.trans.shared.b16 {%0,%1,%2,%3}, [%4];"
        : "=r"(r[0]), "=r"(r[1]), "=r"(r[2]), "=r"(r[3]) : "r"(a));
}
__device__ __forceinline__ void mma16816(float* c, const uint32_t* a, const uint32_t* b) {
    asm volatile(
        "mma.sync.aligned.m16n8k16.row.col.f32.f16.f16.f32 "
        "{%0,%1,%2,%3}, {%4,%5,%6,%7}, {%8,%9}, {%0,%1,%2,%3};"
        : "+f"(c[0]), "+f"(c[1]), "+f"(c[2]), "+f"(c[3])
        : "r"(a[0]), "r"(a[1]), "r"(a[2]), "r"(a[3]), "r"(b[0]), "r"(b[1]));
}

__device__ __forceinline__ uint32_t packh2(float x, float y) {
    __half2 h = __floats2half2_rn(x, y);
    return *reinterpret_cast<uint32_t*>(&h);
}
__device__ __forceinline__ void split2h(float x, float y, uint32_t& hi, uint32_t& lo) {
    __half hx = __float2half_rn(x), hy = __float2half_rn(y);
    hi = ((uint32_t)__half_as_ushort(hx)) | ((uint32_t)__half_as_ushort(hy) << 16);
    lo = packh2(x - __half2float(hx), y - __half2float(hy));
}
__device__ __forceinline__ void store_splith(__half* ph, __half* pl,
                                             size_t idx, float v) {
    __half h = __float2half_rn(v);
    ph[idx] = h;
    pl[idx] = __float2half_rn(v - __half2float(h));
}
__device__ __forceinline__ float warp_sum32(float v) {
#pragma unroll
    for (int o = 16; o > 0; o >>= 1)
        v += __shfl_xor_sync(0xffffffffu, v, o);
    return v;
}

// hi+lo conversion, 4x ILP
__device__ __forceinline__ void cvt4_hl(const float* __restrict__ src,
                                        __half* __restrict__ hi,
                                        __half* __restrict__ lo, int base)
{
#pragma unroll
    for (int k = 0; k < 4; k++) {
        float4 v = ((const float4*)src)[base + k * 256];
        uint32_t a, b, c, d;
        split2h(v.x, v.y, a, c);
        split2h(v.z, v.w, b, d);
        ((uint2*)hi)[base + k * 256] = make_uint2(a, b);
        ((uint2*)lo)[base + k * 256] = make_uint2(c, d);
    }
}
// hi-only conversion, 4x ILP
__device__ __forceinline__ void cvt4_h(const float* __restrict__ src,
                                       __half* __restrict__ hi, int base)
{
#pragma unroll
    for (int k = 0; k < 4; k++) {
        float4 v = ((const float4*)src)[base + k * 256];
        ((uint2*)hi)[base + k * 256] =
            make_uint2(packh2(v.x, v.y), packh2(v.z, v.w));
    }
}

// ---------------------------------------------------------------------------
// Conversions
// ---------------------------------------------------------------------------
__global__ void __launch_bounds__(256)
cvt_w_kernel(const float* w0, const float* w1, const float* w2, const float* w3,
             const float* w4, const float* w5, const float* w6, const float* w7,
             __half* __restrict__ hi, __half* __restrict__ lo)
{
    const int wi = blockIdx.x >> 8;
    const int ib = (blockIdx.x & 255) * 1024 + threadIdx.x;
    const float* src;
    switch (wi) {
        case 0: src = w0; break;  case 1: src = w1; break;
        case 2: src = w2; break;  case 3: src = w3; break;
        case 4: src = w4; break;  case 5: src = w5; break;
        case 6: src = w6; break;  default: src = w7; break;
    }
    const size_t off = (size_t)wi * (INNER * INNER / 4);
    cvt4_hl(src, (__half*)((uint2*)hi + off), (__half*)((uint2*)lo + off), ib);
}

__global__ void __launch_bounds__(256)
cvt_hsenc_kernel(const float* __restrict__ hs, const float* __restrict__ enc,
                 __half* __restrict__ hs_h,
                 __half* __restrict__ enc_h, __half* __restrict__ enc_l)
{
    const int bx = blockIdx.x;
    if (bx < 2048) {
        cvt4_h(hs, hs_h, bx * 1024 + threadIdx.x);
    } else {
        cvt4_hl(enc, enc_h, enc_l, (bx - 2048) * 1024 + threadIdx.x);
    }
}

// ---------------------------------------------------------------------------
// 3-pass MMA block (R11 pipelined style) — for output projections
// ---------------------------------------------------------------------------
#define PADK 40
#define MMA_BLOCK_PIPE(acc, abaseh, abasel, bbaseh, bbasel, ks)               \
    {                                                                         \
        uint32_t a0h[4], a1h[4], a0l[4], a1l[4];                              \
        ldsm_x4(a0h, (abaseh) + (ks) * 2);                                    \
        ldsm_x4(a1h, (abaseh) + (ks) * 2 + 16 * PADK * 2);                    \
        ldsm_x4(a0l, (abasel) + (ks) * 2);                                    \
        ldsm_x4(a1l, (abasel) + (ks) * 2 + 16 * PADK * 2);                    \
        uint32_t bh[2][4], bl[4], bln[4];                                     \
        ldsm_x4(bh[0], (bbaseh) + (ks) * 2);                                  \
        ldsm_x4(bl,    (bbasel) + (ks) * 2);                                  \
        _Pragma("unroll")                                                     \
        for (int nbp = 0; nbp < 4; nbp++) {                                   \
            const int c = nbp & 1;                                            \
            mma16816(acc[0][2 * nbp],     a0h, bh[c]);                        \
            mma16816(acc[0][2 * nbp + 1], a0h, bh[c] + 2);                    \
            mma16816(acc[1][2 * nbp],     a1h, bh[c]);                        \
            mma16816(acc[1][2 * nbp + 1], a1h, bh[c] + 2);                    \
            if (nbp < 3)                                                      \
                ldsm_x4(bh[c ^ 1], (bbaseh) + (ks) * 2 +                      \
                        (nbp + 1) * 16 * PADK * 2);                           \
            mma16816(acc[0][2 * nbp],     a0h, bl);                           \
            mma16816(acc[0][2 * nbp + 1], a0h, bl + 2);                       \
            mma16816(acc[1][2 * nbp],     a1h, bl);                           \
            mma16816(acc[1][2 * nbp + 1], a1h, bl + 2);                       \
            if (nbp < 3)                                                      \
                ldsm_x4(bln, (bbasel) + (ks) * 2 +                            \
                        (nbp + 1) * 16 * PADK * 2);                           \
            mma16816(acc[0][2 * nbp],     a0l, bh[c]);                        \
            mma16816(acc[0][2 * nbp + 1], a0l, bh[c] + 2);                    \
            mma16816(acc[1][2 * nbp],     a1l, bh[c]);                        \
            mma16816(acc[1][2 * nbp + 1], a1l, bh[c] + 2);                    \
            if (nbp < 3) {                                                    \
                bl[0] = bln[0]; bl[1] = bln[1];                               \
                bl[2] = bln[2]; bl[3] = bln[3];                               \
            }                                                                 \
        }                                                                     \
    }

// ---------------------------------------------------------------------------
// v1 3-pass mainloop (4-tile stage: Ah, Al, Wh, Wl) — output projections
// ---------------------------------------------------------------------------
#define GT_TILE  (128 * PADK)
#define GT_STAGE4 (4 * GT_TILE)
#define GEMM1_SMEM_BYTES (2 * GT_STAGE4 * 2)

#define GEMM_V1_MAINLOOP3(Ah, Al, Wh, Wl, K, acc)                             \
    const int tile = t >> 6;                                                  \
    const int l64  = t & 63;                                                  \
    const int lrr  = l64 >> 2;                                                \
    const int lcc  = (l64 & 3) * 8;                                           \
    const __half* gsrc =                                                      \
        (tile == 0) ? Ah : (tile == 1) ? Al : (tile == 2) ? Wh : Wl;          \
    const int rowbase = (tile < 2) ? m0 : n0;                                 \
    const uint32_t smb = smem_u32(sm);                                        \
    const uint32_t sdst0 = smb + ((tile * GT_TILE + lrr * PADK + lcc) << 1);  \
    const __half* gp = gsrc + (size_t)(rowbase + lrr) * K + lcc;              \
    const uint32_t abase_rel = (((wm * 32 + (lane & 15)) * PADK +             \
                                 ((lane >> 4) << 3)) << 1);                   \
    const uint32_t bbase_rel = ((2 * GT_TILE +                                \
        (wn * 64 + (lane & 7) + ((lane >> 4) << 3)) * PADK +                  \
        (((lane >> 3) & 1) << 3)) << 1);                                      \
    const int NT = K / 32;                                                    \
    {                                                                         \
        const __half* g = gp;                                                 \
        _Pragma("unroll")                                                     \
        for (int i = 0; i < 8; i++)                                           \
            CP_ASYNC16(sdst0 + (uint32_t)((i * 16 * PADK) << 1),              \
                       g + (size_t)(i * 16) * K);                             \
        CP_COMMIT();                                                          \
    }                                                                         \
    for (int kt = 0; kt < NT; kt++) {                                         \
        const int b = kt & 1;                                                 \
        if (kt + 1 < NT) {                                                    \
            const __half* g = gp + (kt + 1) * 32;                             \
            const uint32_t d = sdst0 +                                        \
                (uint32_t)((((kt + 1) & 1) * GT_STAGE4) << 1);                \
            _Pragma("unroll")                                                 \
            for (int i = 0; i < 8; i++)                                       \
                CP_ASYNC16(d + (uint32_t)((i * 16 * PADK) << 1),              \
                           g + (size_t)(i * 16) * K);                         \
            CP_COMMIT();                                                      \
            CP_WAIT1();                                                       \
        } else {                                                              \
            CP_WAIT0();                                                       \
        }                                                                     \
        __syncthreads();                                                      \
        const uint32_t stage  = smb + (uint32_t)((b * GT_STAGE4) << 1);       \
        const uint32_t abaseh = stage + abase_rel;                            \
        const uint32_t abasel = abaseh + (GT_TILE << 1);                      \
        const uint32_t bbaseh = stage + bbase_rel;                            \
        const uint32_t bbasel = bbaseh + (GT_TILE << 1);                      \
        _Pragma("unroll")                                                     \
        for (int ks = 0; ks < 32; ks += 16) {                                 \
            MMA_BLOCK_PIPE(acc, abaseh, abasel, bbaseh, bbasel, ks)           \
        }                                                                     \
        __syncthreads();                                                      \
    }

// ---------------------------------------------------------------------------
// Generic v1 3-pass GEMM (fp32 C + optional bias) — vis output projection
// ---------------------------------------------------------------------------
__global__ void __launch_bounds__(256, 2)
gemm_out_kernel(const __half* __restrict__ Ah, const __half* __restrict__ Al,
                const __half* __restrict__ Wh, const __half* __restrict__ Wl,
                const float* __restrict__ bias, float* __restrict__ C,
                int M, int N, int K)
{
    extern __shared__ __half sm[];
    const int t    = threadIdx.x;
    const int lane = t & 31;
    const int wid  = t >> 5;
    const int wm   = wid >> 1;
    const int wn   = wid & 1;
    const int m0   = blockIdx.y * 128;
    const int n0   = blockIdx.x * 128;

    float acc[2][8][4];
#pragma unroll
    for (int i = 0; i < 2; i++)
#pragma unroll
        for (int j = 0; j < 8; j++)
#pragma unroll
            for (int q = 0; q < 4; q++) acc[i][j][q] = 0.f;

    GEMM_V1_MAINLOOP3(Ah, Al, Wh, Wl, K, acc)

    const int r0 = m0 + wm * 32 + (lane >> 2);
    const int c0 = n0 + wn * 64 + (lane & 3) * 2;
#pragma unroll
    for (int mi = 0; mi < 2; mi++) {
        const int r = r0 + mi * 16;
#pragma unroll
        for (int nb = 0; nb < 8; nb++) {
            const int c = c0 + nb * 8;
            float b0 = 0.f, b1 = 0.f;
            if (bias) { b0 = bias[c]; b1 = bias[c + 1]; }
            *(float2*)(C + (size_t)r * N + c) =
                make_float2(acc[mi][nb][0] + b0, acc[mi][nb][1] + b1);
            *(float2*)(C + (size_t)(r + 8) * N + c) =
                make_float2(acc[mi][nb][2] + b0, acc[mi][nb][3] + b1);
        }
    }
}

// ---------------------------------------------------------------------------
// Fused QKV GEMM: fp16x2 (A single, W hi/lo), 3-tile stage, 2-stage pipe.
// Epilogue: RMSNorm + RoPE + sparse scatter (Q hi-only, K/V hi+lo).
// ---------------------------------------------------------------------------
#define GT_STAGE3 (3 * GT_TILE)
#define QKV_SMEM_BYTES (2 * GT_STAGE3 * 2)

__global__ void __launch_bounds__(256, 2)
gemm_qkv_fused_kernel(const __half* __restrict__ Ah,
                      const __half* __restrict__ Wh, const __half* __restrict__ Wl,
                      const float* __restrict__ gq, const float* __restrict__ gk,
                      const float* __restrict__ cosb, const float* __restrict__ sinb,
                      __half* __restrict__ QAh,
                      __half* __restrict__ KAh, __half* __restrict__ KAl,
                      __half* __restrict__ VAh, __half* __restrict__ VAl)
{
    extern __shared__ __half sm[];
    const int t    = threadIdx.x;
    const int lane = t & 31;
    const int wid  = t >> 5;
    const int wm   = wid >> 1;
    const int wn   = wid & 1;
    const int m0   = blockIdx.y * 128;
    const int n0   = blockIdx.x * 128;
    const int K    = INNER;

    float acc[2][8][4];
#pragma unroll
    for (int i = 0; i < 2; i++)
#pragma unroll
        for (int j = 0; j < 8; j++)
#pragma unroll
            for (int q = 0; q < 4; q++) acc[i][j][q] = 0.f;

    // loader: rr = t>>1 (0..127), cc = (t&1)*16; 6 chunks (A, Wh, Wl x2 each)
    const int rr = t >> 1;
    const int cc = (t & 1) * 16;
    const uint32_t smb = smem_u32(sm);
    const uint32_t dA = (uint32_t)((rr * PADK + cc) << 1);
    const __half* gA  = Ah + (size_t)(m0 + rr) * K + cc;
    const __half* gWh = Wh + (size_t)(n0 + rr) * K + cc;
    const __half* gWl = Wl + (size_t)(n0 + rr) * K + cc;

#define QKV_LOAD(kt, b) do {                                               \
    const uint32_t sb = smb + (uint32_t)(((b) * GT_STAGE3) << 1);          \
    const int ko = (kt) * 32;                                              \
    CP_ASYNC16(sb + dA,                              gA  + ko);            \
    CP_ASYNC16(sb + dA + 16,                         gA  + ko + 8);        \
    CP_ASYNC16(sb + dA + (uint32_t)((GT_TILE) << 1),      gWh + ko);       \
    CP_ASYNC16(sb + dA + (uint32_t)((GT_TILE) << 1) + 16, gWh + ko + 8);   \
    CP_ASYNC16(sb + dA + (uint32_t)((2 * GT_TILE) << 1),      gWl + ko);   \
    CP_ASYNC16(sb + dA + (uint32_t)((2 * GT_TILE) << 1) + 16, gWl + ko + 8);\
    CP_COMMIT();                                                           \
} while (0)

    QKV_LOAD(0, 0);

    const uint32_t abase_rel = (((wm * 32 + (lane & 15)) * PADK +
                                 ((lane >> 4) << 3)) << 1);
    const uint32_t bbase_rel = ((GT_TILE +
        (wn * 64 + (lane & 7) + ((lane >> 4) << 3)) * PADK +
        (((lane >> 3) & 1) << 3)) << 1);

    const int NT = K / 32;
    for (int kt = 0; kt < NT; kt++) {
        const int b = kt & 1;
        if (kt + 1 < NT) {
            QKV_LOAD(kt + 1, (kt + 1) & 1);
            CP_WAIT1();
        } else {
            CP_WAIT0();
        }
        __syncthreads();

        const uint32_t stage  = smb + (uint32_t)((b * GT_STAGE3) << 1);
        const uint32_t abaseh = stage + abase_rel;
        const uint32_t bbaseh = stage + bbase_rel;
        const uint32_t bbasel = bbaseh + (GT_TILE << 1);

#pragma unroll
        for (int ks = 0; ks < 32; ks += 16) {
            uint32_t a0[4], a1[4];
            ldsm_x4(a0, abaseh + ks * 2);
            ldsm_x4(a1, abaseh + ks * 2 + 16 * PADK * 2);
            uint32_t bh[2][4], bl[4], bln[4];
            ldsm_x4(bh[0], bbaseh + ks * 2);
            ldsm_x4(bl,    bbasel + ks * 2);
#pragma unroll
            for (int nbp = 0; nbp < 4; nbp++) {
                const int c = nbp & 1;
                mma16816(acc[0][2 * nbp],     a0, bh[c]);
                mma16816(acc[0][2 * nbp + 1], a0, bh[c] + 2);
                mma16816(acc[1][2 * nbp],     a1, bh[c]);
                mma16816(acc[1][2 * nbp + 1], a1, bh[c] + 2);
                if (nbp < 3)
                    ldsm_x4(bh[c ^ 1], bbaseh + ks * 2 + (nbp + 1) * 16 * PADK * 2);
                mma16816(acc[0][2 * nbp],     a0, bl);
                mma16816(acc[0][2 * nbp + 1], a0, bl + 2);
                mma16816(acc[1][2 * nbp],     a1, bl);
                mma16816(acc[1][2 * nbp + 1], a1, bl + 2);
                if (nbp < 3) {
                    ldsm_x4(bln, bbasel + ks * 2 + (nbp + 1) * 16 * PADK * 2);
                    bl[0] = bln[0]; bl[1] = bln[1];
                    bl[2] = bln[2]; bl[3] = bln[3];
                }
            }
        }
        __syncthreads();
    }

    // ---- fused epilogue ----
    const int nhead = (n0 >> 6) + wn;
    const int sec   = nhead >> 4;           // 0=Q 1=K 2=V
    const int hh    = nhead & 15;
    const int dq    = (lane & 3) * 2;
    const int rbase = m0 + wm * 32 + (lane >> 2);

    const float* gvec = (sec == 0) ? gq : gk;
    const float qscale = (sec == 0) ? ATTN_SCALE : 1.0f;

#pragma unroll
    for (int mi = 0; mi < 2; mi++) {
#pragma unroll
        for (int half = 0; half < 2; half++) {
            const int row = rbase + mi * 16 + half * 8;
            const int vi = half * 2;
            const int j = row & 7, tt = row >> 3;
            const size_t dstb = (((size_t)(j * NUM_HEADS + hh)) * STOT + tt) * HEAD_DIM;

            if (sec == 2) {
                uint32_t* oh32 = (uint32_t*)(VAh + dstb);
                uint32_t* ol32 = (uint32_t*)(VAl + dstb);
#pragma unroll
                for (int nb = 0; nb < 8; nb++) {
                    uint32_t hi, lo;
                    split2h(acc[mi][nb][vi], acc[mi][nb][vi + 1], hi, lo);
                    const int d = dq + nb * 8;
                    oh32[d >> 1] = hi;
                    ol32[d >> 1] = lo;
                }
            } else {
                float ss = 0.f;
#pragma unroll
                for (int nb = 0; nb < 8; nb++) {
                    ss += acc[mi][nb][vi] * acc[mi][nb][vi];
                    ss += acc[mi][nb][vi + 1] * acc[mi][nb][vi + 1];
                }
                ss += __shfl_xor_sync(0xffffffffu, ss, 1);
                ss += __shfl_xor_sync(0xffffffffu, ss, 2);
                const float rms = rsqrtf(ss * (1.f / HEAD_DIM) + EPS_RMS);

                const float* cb = cosb + (size_t)row * HEAD_DIM;
                const float* sb = sinb + (size_t)row * HEAD_DIM;
#pragma unroll
                for (int nb = 0; nb < 4; nb++) {
                    const int d0 = dq + nb * 8;
                    const int d1 = d0 + 32;
                    const float x00 = acc[mi][nb][vi]         * rms * gvec[d0];
                    const float x01 = acc[mi][nb][vi + 1]     * rms * gvec[d0 + 1];
                    const float x10 = acc[mi][nb + 4][vi]     * rms * gvec[d1];
                    const float x11 = acc[mi][nb + 4][vi + 1] * rms * gvec[d1 + 1];
                    const float y00 = (x00 * cb[d0]     - x10 * sb[d0])     * qscale;
                    const float y01 = (x01 * cb[d0 + 1] - x11 * sb[d0 + 1]) * qscale;
                    const float y10 = (x10 * cb[d1]     + x00 * sb[d1])     * qscale;
                    const float y11 = (x11 * cb[d1 + 1] + x01 * sb[d1 + 1]) * qscale;
                    if (sec == 0) {
                        uint32_t* oh32 = (uint32_t*)(QAh + dstb);
                        oh32[d0 >> 1] = packh2(y00, y01);
                        oh32[d1 >> 1] = packh2(y10, y11);
                    } else {
                        uint32_t* oh32 = (uint32_t*)(KAh + dstb);
                        uint32_t* ol32 = (uint32_t*)(KAl + dstb);
                        uint32_t hi, lo;
                        split2h(y00, y01, hi, lo);
                        oh32[d0 >> 1] = hi;  ol32[d0 >> 1] = lo;
                        split2h(y10, y11, hi, lo);
                        oh32[d1 >> 1] = hi;  ol32[d1 >> 1] = lo;
                    }
                }
            }
        }
    }
}

// ---------------------------------------------------------------------------
// GEMM v2: 3-pass, 256x128 CTA, 512 threads, 3-stage, K-split (small-M GEMMs)
// ---------------------------------------------------------------------------
#define V2_TILE_A (256 * PADK)
#define V2_TILE_W (128 * PADK)
#define V2_STAGE (2 * V2_TILE_A + 2 * V2_TILE_W)
#define GEMM2_SMEM_BYTES (3 * V2_STAGE * 2)

__global__ void __launch_bounds__(512, 1)
gemm_v2_kernel(const __half* __restrict__ Ah, const __half* __restrict__ Al,
               const __half* __restrict__ Wh, const __half* __restrict__ Wl,
               float* __restrict__ C, int M, int N, int K, int kparts)
{
    extern __shared__ __half sm[];
    const int t    = threadIdx.x;
    const int lane = t & 31;
    const int wid  = t >> 5;
    const int wm   = wid >> 1;
    const int wn   = wid & 1;
    const int m0   = blockIdx.y * 256;
    const int n0   = blockIdx.x * 128;

    const int KC    = K / kparts;
    const int kbase = blockIdx.z * KC;
    const int NT    = KC / 32;

    float acc[2][8][4];
#pragma unroll
    for (int i = 0; i < 2; i++)
#pragma unroll
        for (int j = 0; j < 8; j++)
#pragma unroll
            for (int q = 0; q < 4; q++) acc[i][j][q] = 0.f;

    const int rr = t >> 2;
    const int cc = (t & 3) * 8;
    const uint32_t smb = smem_u32(sm);

    const __half* pA0 = Ah + (size_t)(m0 + rr)       * K + kbase + cc;
    const __half* pA1 = Ah + (size_t)(m0 + rr + 128) * K + kbase + cc;
    const __half* pL0 = Al + (size_t)(m0 + rr)       * K + kbase + cc;
    const __half* pL1 = Al + (size_t)(m0 + rr + 128) * K + kbase + cc;
    const __half* pWh = Wh + (size_t)(n0 + rr)       * K + kbase + cc;
    const __half* pWl = Wl + (size_t)(n0 + rr)       * K + kbase + cc;

    const uint32_t dA0 = (uint32_t)((rr * PADK + cc) << 1);
    const uint32_t dA1 = (uint32_t)(((rr + 128) * PADK + cc) << 1);
    const uint32_t dL0 = dA0 + (uint32_t)(V2_TILE_A << 1);
    const uint32_t dL1 = dA1 + (uint32_t)(V2_TILE_A << 1);
    const uint32_t dWh = dA0 + (uint32_t)((2 * V2_TILE_A) << 1);
    const uint32_t dWl = dA0 + (uint32_t)(((2 * V2_TILE_A) + V2_TILE_W) << 1);

#define V2_LOAD(kt, stg) do {                                              \
    const uint32_t sb = smb + (uint32_t)(((stg) * V2_STAGE) << 1);         \
    const int ko = (kt) * 32;                                              \
    CP_ASYNC16(sb + dA0, pA0 + ko);                                        \
    CP_ASYNC16(sb + dA1, pA1 + ko);                                        \
    CP_ASYNC16(sb + dL0, pL0 + ko);                                        \
    CP_ASYNC16(sb + dL1, pL1 + ko);                                        \
    CP_ASYNC16(sb + dWh, pWh + ko);                                        \
    CP_ASYNC16(sb + dWl, pWl + ko);                                        \
    CP_COMMIT();                                                           \
} while (0)

    V2_LOAD(0, 0);
    V2_LOAD(1, 1);

    const uint32_t abase_rel = (uint32_t)((((wm * 32 + (lane & 15)) * PADK +
                                            ((lane >> 4) << 3))) << 1);
    const uint32_t bbase_rel = (uint32_t)(((2 * V2_TILE_A +
                     (wn * 64 + (lane & 7) + ((lane >> 4) << 3)) * PADK +
                     (((lane >> 3) & 1) << 3))) << 1);

    int stg = 0;
    for (int kt = 0; kt < NT; kt++) {
        if (kt + 2 < NT) {
            const int ps = (stg + 2 >= 3) ? (stg - 1) : (stg + 2);
            V2_LOAD(kt + 2, ps);
            CP_WAIT2();
        } else {
            CP_WAIT0();
        }
        __syncthreads();

        const uint32_t stage  = smb + (uint32_t)((stg * V2_STAGE) << 1);
        const uint32_t abaseh = stage + abase_rel;
        const uint32_t abasel = abaseh + (uint32_t)(V2_TILE_A << 1);
        const uint32_t bbaseh = stage + bbase_rel;
        const uint32_t bbasel = bbaseh + (uint32_t)(V2_TILE_W << 1);

#pragma unroll
        for (int ks = 0; ks < 32; ks += 16) {
            MMA_BLOCK_PIPE(acc, abaseh, abasel, bbaseh, bbasel, ks)
        }
        __syncthreads();
        stg = (stg + 1 >= 3) ? 0 : (stg + 1);
    }

    float* Cz = C + (size_t)blockIdx.z * M * N;
    const int r0 = m0 + wm * 32 + (lane >> 2);
    const int c0 = n0 + wn * 64 + (lane & 3) * 2;
#pragma unroll
    for (int mi = 0; mi < 2; mi++) {
        const int r = r0 + mi * 16;
#pragma unroll
        for (int nb = 0; nb < 8; nb++) {
            const int c = c0 + nb * 8;
            *(float2*)(Cz + (size_t)r * N + c) =
                make_float2(acc[mi][nb][0], acc[mi][nb][1]);
            *(float2*)(Cz + (size_t)(r + 8) * N + c) =
                make_float2(acc[mi][nb][2], acc[mi][nb][3]);
        }
    }
}

// ---------------------------------------------------------------------------
// K-split reduce (with bias)
// ---------------------------------------------------------------------------
__global__ void __launch_bounds__(256)
reduce4_kernel(const float* __restrict__ part, const float* __restrict__ bias,
               float* __restrict__ out, int MN, int N)
{
    const int i = blockIdx.x * 256 + threadIdx.x;
    if (i * 4 >= MN) return;
    const int q = MN / 4;
    float4 a = ((const float4*)part)[i];
    float4 b = ((const float4*)part)[i + q];
    float4 c = ((const float4*)part)[i + 2 * q];
    float4 d = ((const float4*)part)[i + 3 * q];
    float4 r = make_float4(a.x + b.x + c.x + d.x, a.y + b.y + c.y + d.y,
                           a.z + b.z + c.z + d.z, a.w + b.w + c.w + d.w);
    if (bias) {
        const int col = (i * 4) % N;
        r.x += bias[col];  r.y += bias[col + 1];
        r.z += bias[col + 2];  r.w += bias[col + 3];
    }
    ((float4*)out)[i] = r;
}

// ---------------------------------------------------------------------------
// RMSNorm + broadcast scatter (text): Q hi-only, K/V hi+lo
// ---------------------------------------------------------------------------
__global__ void __launch_bounds__(256)
enc_post_kernel(const float* __restrict__ part,
                const float* __restrict__ gaq, const float* __restrict__ gak,
                __half* __restrict__ QAh,
                __half* __restrict__ KAh, __half* __restrict__ KAl,
                __half* __restrict__ VAh, __half* __restrict__ VAl)
{
    const int warp = (blockIdx.x * blockDim.x + threadIdx.x) >> 5;
    const int lane = threadIdx.x & 31;
    const int tt = warp >> 4;
    const int h  = warp & 15;
    if (tt >= T_LEN) return;

    const size_t src = (size_t)tt * INNER3 + h * HEAD_DIM;
    const size_t PQ = (size_t)T_LEN * INNER3;
    float a0 = 0.f, a1 = 0.f, b0 = 0.f, b1 = 0.f, v0 = 0.f, v1 = 0.f;
#pragma unroll
    for (int z = 0; z < 4; z++) {
        const float* p = part + z * PQ + src;
        a0 += p[lane];              a1 += p[lane + 32];
        b0 += p[INNER + lane];      b1 += p[INNER + lane + 32];
        v0 += p[2*INNER + lane];    v1 += p[2*INNER + lane + 32];
    }

    float ra = rsqrtf(warp_sum32(a0 * a0 + a1 * a1) * (1.f / HEAD_DIM) + EPS_RMS);
    float rb = rsqrtf(warp_sum32(b0 * b0 + b1 * b1) * (1.f / HEAD_DIM) + EPS_RMS);

    a0 *= ra * gaq[lane] * ATTN_SCALE;  a1 *= ra * gaq[lane + 32] * ATTN_SCALE;
    b0 *= rb * gak[lane];               b1 *= rb * gak[lane + 32];

#pragma unroll
    for (int j = 0; j < SPARSE_N; j++) {
        const size_t dst =
            (((size_t)(j * NUM_HEADS + h)) * STOT + G_LEN + tt) * HEAD_DIM;
        QAh[dst + lane]      = __float2half_rn(a0);
        QAh[dst + lane + 32] = __float2half_rn(a1);
        store_splith(KAh, KAl, dst + lane,      b0);
        store_splith(KAh, KAl, dst + lane + 32, b1);
        store_splith(VAh, VAl, dst + lane,      v0);
        store_splith(VAh, VAl, dst + lane + 32, v1);
    }
}

// ---------------------------------------------------------------------------
// Flash attention fp16x2: Q single, K/V hi/lo; static-max softmax;
// P single (no split); fused vis gather. BQ=256, 512 threads.
// ---------------------------------------------------------------------------
#define APAD 72
#define AQ_ELEMS (256 * APAD)
#define KV_TILE  (64 * APAD)
#define KV_STAGE (4 * KV_TILE)
#define ATT_SM_BYTES ((AQ_ELEMS + 2 * KV_STAGE) * 2)

__global__ void __launch_bounds__(512, 1)
attn_mma_kernel(const __half* __restrict__ Qhg,
                const __half* __restrict__ Khg, const __half* __restrict__ Klg,
                const __half* __restrict__ Vhg, const __half* __restrict__ Vlg,
                float* __restrict__ OA,
                __half* __restrict__ vis_h, __half* __restrict__ vis_l)
{
    extern __shared__ __half smA[];
    const int t    = threadIdx.x;
    const int lane = t & 31;
    const int w    = t >> 5;
    const int jh   = blockIdx.y;
    const int q0   = blockIdx.x * 256;
    const size_t base = (size_t)jh * STOT * HEAD_DIM;

    const uint32_t smb = smem_u32(smA);

    const int tile = t >> 7;
    const int l128 = t & 127;
    const int krr  = l128 >> 3;
    const int kcc  = (l128 & 7) * 8;
    const __half* kvsrc =
        (tile == 0) ? Khg : (tile == 1) ? Klg : (tile == 2) ? Vhg : Vlg;
    const uint32_t kvdst0 = smb + ((AQ_ELEMS + tile * KV_TILE + krr * APAD + kcc) << 1);

    {
        const __half* g = kvsrc + base + (size_t)krr * 64 + kcc;
#pragma unroll
        for (int i = 0; i < 4; i++)
            CP_ASYNC16(kvdst0 + (uint32_t)((i * 16 * APAD) << 1),
                       g + (size_t)(i * 16) * 64);
        CP_COMMIT();
    }

    // Q tile 256x64 (single precision fp16)
    {
        const int row = t >> 1, c0 = (t & 1) * 32;
        const __half* gh = Qhg + base + (size_t)(q0 + row) * 64 + c0;
        __half* sh = smA + row * APAD + c0;
#pragma unroll
        for (int c = 0; c < 32; c += 8)
            *(uint4*)(sh + c) = *(const uint4*)(gh + c);
    }

    float o[8][4];
#pragma unroll
    for (int i = 0; i < 8; i++)
#pragma unroll
        for (int j = 0; j < 4; j++) o[i][j] = 0.f;
    float l0r = 0.f, l1r = 0.f;

    const uint32_t qfrag = smb + (((w * 16 + (lane & 15)) * APAD + ((lane >> 4) << 3)) << 1);
    const uint32_t kfrag_rel = ((((lane & 7) + ((lane >> 4) << 3)) * APAD + (((lane >> 3) & 1) << 3)) << 1);
    const uint32_t vfrag_rel = (((2 * KV_TILE) + ((lane & 7) + (((lane >> 3) & 1) << 3)) * APAD + ((lane >> 4) << 3)) << 1);

    for (int kt = 0; kt < 20; kt++) {
        const int b = kt & 1;
        if (kt + 1 < 20) {
            const __half* g = kvsrc + base + (size_t)((kt + 1) * 64 + krr) * 64 + kcc;
            const uint32_t d = kvdst0 + (uint32_t)((((kt + 1) & 1) * KV_STAGE) << 1);
#pragma unroll
            for (int i = 0; i < 4; i++)
                CP_ASYNC16(d + (uint32_t)((i * 16 * APAD) << 1),
                           g + (size_t)(i * 16) * 64);
            CP_COMMIT();
            CP_WAIT1();
        } else {
            CP_WAIT0();
        }
        __syncthreads();

        const uint32_t kvstage = smb + (uint32_t)(((AQ_ELEMS + b * KV_STAGE)) << 1);
        const uint32_t kfragh = kvstage + kfrag_rel;
        const uint32_t kfragl = kfragh + (KV_TILE << 1);
        const uint32_t vfrag  = kvstage + vfrag_rel;

        float s[8][4];
#pragma unroll
        for (int i = 0; i < 8; i++)
#pragma unroll
            for (int j = 0; j < 4; j++) s[i][j] = 0.f;

        // ---- scores: q_h * (k_h + k_l), 2 passes ----
#pragma unroll
        for (int ks = 0; ks < 64; ks += 16) {
            uint32_t ah[4];
            ldsm_x4(ah, qfrag + ks * 2);
            uint32_t kh[2][4], kl[4], kln[4];
            ldsm_x4(kh[0], kfragh + ks * 2);
            ldsm_x4(kl,    kfragl + ks * 2);
#pragma unroll
            for (int nbp = 0; nbp < 4; nbp++) {
                const int c = nbp & 1;
                mma16816(s[2 * nbp],     ah, kh[c]);
                mma16816(s[2 * nbp + 1], ah, kh[c] + 2);
                if (nbp < 3)
                    ldsm_x4(kh[c ^ 1], kfragh + ks * 2 + (nbp + 1) * 16 * APAD * 2);
                mma16816(s[2 * nbp],     ah, kl);
                mma16816(s[2 * nbp + 1], ah, kl + 2);
                if (nbp < 3) {
                    ldsm_x4(kln, kfragl + ks * 2 + (nbp + 1) * 16 * APAD * 2);
                    kl[0] = kln[0]; kl[1] = kln[1];
                    kl[2] = kln[2]; kl[3] = kln[3];
                }
            }
        }

        // ---- static-max softmax ----
        float rs0 = 0.f, rs1 = 0.f;
#pragma unroll
        for (int nb = 0; nb < 8; nb++) {
            s[nb][0] = __expf(s[nb][0] - SMAX);  rs0 += s[nb][0];
            s[nb][1] = __expf(s[nb][1] - SMAX);  rs0 += s[nb][1];
            s[nb][2] = __expf(s[nb][2] - SMAX);  rs1 += s[nb][2];
            s[nb][3] = __expf(s[nb][3] - SMAX);  rs1 += s[nb][3];
        }
        rs0 += __shfl_xor_sync(0xffffffffu, rs0, 1);
        rs0 += __shfl_xor_sync(0xffffffffu, rs0, 2);
        rs1 += __shfl_xor_sync(0xffffffffu, rs1, 1);
        rs1 += __shfl_xor_sync(0xffffffffu, rs1, 2);
        l0r += rs0;
        l1r += rs1;

        // ---- PV: p_h * (v_h + v_l), 2 passes ----
#pragma unroll
        for (int kb2 = 0; kb2 < 4; kb2++) {
            uint32_t ph[4];
            ph[0] = packh2(s[2 * kb2][0],     s[2 * kb2][1]);
            ph[1] = packh2(s[2 * kb2][2],     s[2 * kb2][3]);
            ph[2] = packh2(s[2 * kb2 + 1][0], s[2 * kb2 + 1][1]);
            ph[3] = packh2(s[2 * kb2 + 1][2], s[2 * kb2 + 1][3]);
            const uint32_t vb = vfrag + kb2 * 16 * APAD * 2;
            uint32_t vh[2][4], vl[4], vln[4];
            ldsm_x4_t(vh[0], vb);
            ldsm_x4_t(vl, vb + (KV_TILE << 1));
#pragma unroll
            for (int dbp = 0; dbp < 4; dbp++) {
                const int c = dbp & 1;
                mma16816(o[2 * dbp],     ph, vh[c]);
                mma16816(o[2 * dbp + 1], ph, vh[c] + 2);
                if (dbp < 3)
                    ldsm_x4_t(vh[c ^ 1], vb + (dbp + 1) * 16 * 2);
                mma16816(o[2 * dbp],     ph, vl);
                mma16816(o[2 * dbp + 1], ph, vl + 2);
                if (dbp < 3) {
                    ldsm_x4_t(vln, vb + (KV_TILE << 1) + (dbp + 1) * 16 * 2);
                    vl[0] = vln[0]; vl[1] = vln[1];
                    vl[2] = vln[2]; vl[3] = vln[3];
                }
            }
        }
        __syncthreads();
    }

    const float inv0 = 1.f / l0r, inv1 = 1.f / l1r;
    const int row = q0 + w * 16 + (lane >> 2);
    const int col = (lane & 3) * 2;
    if (blockIdx.x < 4) {
        const int j = jh >> 4, h = jh & 15;
        uint32_t* vh32 = (uint32_t*)vis_h;
        uint32_t* vl32 = (uint32_t*)vis_l;
        const size_t b0 = ((size_t)row * 8 + j) * INNER + h * 64;
        const size_t b1 = ((size_t)(row + 8) * 8 + j) * INNER + h * 64;
#pragma unroll
        for (int db = 0; db < 8; db++) {
            uint32_t hi, lo;
            split2h(o[db][0] * inv0, o[db][1] * inv0, hi, lo);
            vh32[(b0 + db * 8 + col) >> 1] = hi;
            vl32[(b0 + db * 8 + col) >> 1] = lo;
            split2h(o[db][2] * inv1, o[db][3] * inv1, hi, lo);
            vh32[(b1 + db * 8 + col) >> 1] = hi;
            vl32[(b1 + db * 8 + col) >> 1] = lo;
        }
    } else {
#pragma unroll
        for (int db = 0; db < 8; db++) {
            *(float2*)(OA + base + (size_t)row * 64 + db * 8 + col) =
                make_float2(o[db][0] * inv0, o[db][1] * inv0);
            *(float2*)(OA + base + (size_t)(row + 8) * 64 + db * 8 + col) =
                make_float2(o[db][2] * inv1, o[db][3] * inv1);
        }
    }
}

// ---------------------------------------------------------------------------
// Gather text rows -> fp16 hi/lo (mean over j)
// ---------------------------------------------------------------------------
__global__ void __launch_bounds__(256)
gather_txt_kernel(const float* __restrict__ OA,
                  __half* __restrict__ th, __half* __restrict__ tl)
{
    const int i = blockIdx.x * 256 + threadIdx.x;
    const int idx = i * 4;
    const int tt = idx >> 10, e = idx & 1023;
    const int h = e >> 6, d = e & 63;
    float4 acc = make_float4(0.f, 0.f, 0.f, 0.f);
#pragma unroll
    for (int j = 0; j < SPARSE_N; j++) {
        float4 v = *(const float4*)(OA +
            (((size_t)(j * NUM_HEADS + h)) * STOT + G_LEN + tt) * HEAD_DIM + d);
        acc.x += v.x; acc.y += v.y; acc.z += v.z; acc.w += v.w;
    }
    acc.x *= 0.125f; acc.y *= 0.125f; acc.z *= 0.125f; acc.w *= 0.125f;
    uint32_t h01, l01, h23, l23;
    split2h(acc.x, acc.y, h01, l01);
    split2h(acc.z, acc.w, h23, l23);
    ((uint2*)th)[i] = make_uint2(h01, h23);
    ((uint2*)tl)[i] = make_uint2(l01, l23);
}

// ---------------------------------------------------------------------------
// kernel_launch
// ---------------------------------------------------------------------------
extern "C" void kernel_launch(void* const* d_in, const int* in_sizes, int n_in,
                              void* d_out, int out_size)
{
    const float* hs   = (const float*)d_in[0];
    const float* enc  = (const float*)d_in[1];
    const float* bout  = (const float*)d_in[9];
    const float* baout = (const float*)d_in[11];
    const float* gq   = (const float*)d_in[12];
    const float* gk   = (const float*)d_in[13];
    const float* gaq  = (const float*)d_in[14];
    const float* gak  = (const float*)d_in[15];
    const float* rc   = (const float*)d_in[16];
    const float* rs   = (const float*)d_in[17];
    float* out = (float*)d_out;

    float *encpart, *txtpart, *OA;
    __half *hs_h, *enc_h, *enc_l, *w_h, *w_l;
    __half *vis_h, *vis_l, *txt_h, *txt_l;
    __half *QAh, *KAh, *KAl, *VAh, *VAl;
    cudaGetSymbolAddress((void**)&encpart, g_encpart);
    cudaGetSymbolAddress((void**)&txtpart, g_txtpart);
    cudaGetSymbolAddress((void**)&OA,    g_OA);
    cudaGetSymbolAddress((void**)&hs_h,  g_hs_h);
    cudaGetSymbolAddress((void**)&enc_h, g_enc_h);
    cudaGetSymbolAddress((void**)&enc_l, g_enc_l);
    cudaGetSymbolAddress((void**)&w_h,   g_w_h);
    cudaGetSymbolAddress((void**)&w_l,   g_w_l);
    cudaGetSymbolAddress((void**)&vis_h, g_vis_h);
    cudaGetSymbolAddress((void**)&vis_l, g_vis_l);
    cudaGetSymbolAddress((void**)&txt_h, g_txt_h);
    cudaGetSymbolAddress((void**)&txt_l, g_txt_l);
    cudaGetSymbolAddress((void**)&QAh,   g_QAh);
    cudaGetSymbolAddress((void**)&KAh,   g_KAh);
    cudaGetSymbolAddress((void**)&KAl,   g_KAl);
    cudaGetSymbolAddress((void**)&VAh,   g_VAh);
    cudaGetSymbolAddress((void**)&VAl,   g_VAl);

    cudaFuncSetAttribute(gemm_out_kernel,
                         cudaFuncAttributeMaxDynamicSharedMemorySize, GEMM1_SMEM_BYTES);
    cudaFuncSetAttribute(gemm_qkv_fused_kernel,
                         cudaFuncAttributeMaxDynamicSharedMemorySize, QKV_SMEM_BYTES);
    cudaFuncSetAttribute(gemm_v2_kernel,
                         cudaFuncAttributeMaxDynamicSharedMemorySize, GEMM2_SMEM_BYTES);
    cudaFuncSetAttribute(attn_mma_kernel,
                         cudaFuncAttributeMaxDynamicSharedMemorySize, ATT_SM_BYTES);

    const size_t WS = (size_t)INNER * INNER;

    // [0] weight conversions, [1] hs+enc conversions
    cvt_w_kernel<<<2048, 256>>>(
        (const float*)d_in[2], (const float*)d_in[3], (const float*)d_in[4],
        (const float*)d_in[5], (const float*)d_in[6], (const float*)d_in[7],
        (const float*)d_in[8], (const float*)d_in[10], w_h, w_l);
    cvt_hsenc_kernel<<<2112, 256>>>(hs, enc, hs_h, enc_h, enc_l);

    // [2] enc QKV GEMM (3-pass v2, K-split x4), [3] enc post (fused reduce)
    gemm_v2_kernel<<<dim3(INNER3 / 128, 1, 4), 512, GEMM2_SMEM_BYTES>>>(
        enc_h, enc_l, w_h + 3 * WS, w_l + 3 * WS, encpart, T_LEN, INNER3, INNER, 4);
    enc_post_kernel<<<(T_LEN * NUM_HEADS) / 8, 256>>>(
        encpart, gaq, gak, QAh, KAh, KAl, VAh, VAl);

    // [4] big QKV GEMM (2-pass fp16, fused epilogue)
    gemm_qkv_fused_kernel<<<dim3(INNER3 / 128, S_LEN / 128), 256, QKV_SMEM_BYTES>>>(
        hs_h, w_h + 0 * WS, w_l + 0 * WS,
        gq, gk, rc, rs, QAh, KAh, KAl, VAh, VAl);

    // [5] attention (2-pass fp16, static-max softmax, fused vis gather)
    attn_mma_kernel<<<dim3(STOT / 256, NJH), 512, ATT_SM_BYTES>>>(
        QAh, KAh, KAl, VAh, VAl, OA, vis_h, vis_l);

    // [6] text gather
    gather_txt_kernel<<<(T_LEN * INNER / 4) / 256, 256>>>(OA, txt_h, txt_l);

    // [7] vis out GEMM (3-pass)
    gemm_out_kernel<<<dim3(INNER / 128, S_LEN / 128), 256, GEMM1_SMEM_BYTES>>>(
        vis_h, vis_l, w_h + 6 * WS, w_l + 6 * WS, bout, out, S_LEN, INNER, INNER);

    // [8] txt out GEMM (3-pass v2, K-split x4), [9] reduce with bias
    gemm_v2_kernel<<<dim3(INNER / 128, 1, 4), 512, GEMM2_SMEM_BYTES>>>(
        txt_h, txt_l, w_h + 7 * WS, w_l + 7 * WS, txtpart, T_LEN, INNER, INNER, 4);
    reduce4_kernel<<<(T_LEN * INNER / 4) / 256, 256>>>(
        txtpart, baout, out + (size_t)S_LEN * INNER, T_LEN * INNER, INNER);
}

// round 14
// speedup vs baseline: 1.2887x; 1.0429x over previous
#include <cuda_runtime.h>
#include <cuda_fp16.h>
#include <math.h>
#include <stdint.h>

// ---------------------------------------------------------------------------
// Problem constants
// ---------------------------------------------------------------------------
#define S_LEN     8192
#define T_LEN     256
#define NUM_HEADS 16
#define HEAD_DIM  64
#define INNER     1024
#define INNER3    3072
#define SPARSE_N  8
#define G_LEN     1024
#define STOT      1280
#define NJH       128
#define EPS_RMS   1e-5f
#define ATTN_SCALE 0.125f
#define SMAX      8.0f
#define ATT_ELEMS (NJH * STOT * HEAD_DIM)

// ---------------------------------------------------------------------------
// Static device scratch
// ---------------------------------------------------------------------------
__device__ float g_encpart[4 * T_LEN * INNER3];
__device__ float g_txtpart[4 * T_LEN * INNER];
__device__ float g_OA[ATT_ELEMS];

__device__ __half g_hs_h[S_LEN * INNER];
__device__ __half g_enc_h[T_LEN * INNER];
__device__ __half g_enc_l[T_LEN * INNER];
__device__ __half g_w_h[8 * INNER * INNER];
__device__ __half g_w_l[8 * INNER * INNER];
__device__ __half g_vis_h[S_LEN * INNER];
__device__ __half g_txt_h[T_LEN * INNER];
__device__ __half g_txt_l[T_LEN * INNER];
__device__ __half g_QAh[ATT_ELEMS];
__device__ __half g_KAh[ATT_ELEMS];
__device__ __half g_KAl[ATT_ELEMS];
__device__ __half g_VAh[ATT_ELEMS];
__device__ __half g_VAl[ATT_ELEMS];

// ---------------------------------------------------------------------------
// Helpers
// ---------------------------------------------------------------------------
__device__ __forceinline__ uint32_t smem_u32(const void* p) {
    uint32_t a;
    asm("{ .reg .u64 t; cvta.to.shared.u64 t, %1; cvt.u32.u64 %0, t; }"
        : "=r"(a) : "l"(p));
    return a;
}

#define CP_ASYNC16(dst, src) \
    asm volatile("cp.async.cg.shared.global [%0], [%1], 16;" :: "r"(dst), "l"(src))
#define CP_COMMIT() asm volatile("cp.async.commit_group;" ::: "memory")
#define CP_WAIT0()  asm volatile("cp.async.wait_group 0;" ::: "memory")
#define CP_WAIT1()  asm volatile("cp.async.wait_group 1;" ::: "memory")
#define CP_WAIT2()  asm volatile("cp.async.wait_group 2;" ::: "memory")

__device__ __forceinline__ void ldsm_x4(uint32_t* r, uint32_t a) {
    asm volatile("ldmatrix.sync.aligned.m8n8.x4.shared.b16 {%0,%1,%2,%3}, [%4];"
        : "=r"(r[0]), "=r"(r[1]), "=r"(r[2]), "=r"(r[3]) : "r"(a));
}
__device__ __forceinline__ void ldsm_x4_t(uint32_t* r, uint32_t a) {
    asm volatile("ldmatrix.sync.aligned.m8n8.x4.trans.shared.b16 {%0,%1,%2,%3}, [%4];"
        : "=r"(r[0]), "=r"(r[1]), "=r"(r[2]), "=r"(r[3]) : "r"(a));
}
__device__ __forceinline__ void mma16816(float* c, const uint32_t* a, const uint32_t* b) {
    asm volatile(
        "mma.sync.aligned.m16n8k16.row.col.f32.f16.f16.f32 "
        "{%0,%1,%2,%3}, {%4,%5,%6,%7}, {%8,%9}, {%0,%1,%2,%3};"
        : "+f"(c[0]), "+f"(c[1]), "+f"(c[2]), "+f"(c[3])
        : "r"(a[0]), "r"(a[1]), "r"(a[2]), "r"(a[3]), "r"(b[0]), "r"(b[1]));
}

__device__ __forceinline__ uint32_t packh2(float x, float y) {
    __half2 h = __floats2half2_rn(x, y);
    return *reinterpret_cast<uint32_t*>(&h);
}
__device__ __forceinline__ void split2h(float x, float y, uint32_t& hi, uint32_t& lo) {
    __half hx = __float2half_rn(x), hy = __float2half_rn(y);
    hi = ((uint32_t)__half_as_ushort(hx)) | ((uint32_t)__half_as_ushort(hy) << 16);
    lo = packh2(x - __half2float(hx), y - __half2float(hy));
}
__device__ __forceinline__ void store_splith(__half* ph, __half* pl,
                                             size_t idx, float v) {
    __half h = __float2half_rn(v);
    ph[idx] = h;
    pl[idx] = __float2half_rn(v - __half2float(h));
}
__device__ __forceinline__ float warp_sum32(float v) {
#pragma unroll
    for (int o = 16; o > 0; o >>= 1)
        v += __shfl_xor_sync(0xffffffffu, v, o);
    return v;
}

__device__ __forceinline__ void cvt4_hl(const float* __restrict__ src,
                                        __half* __restrict__ hi,
                                        __half* __restrict__ lo, int base)
{
#pragma unroll
    for (int k = 0; k < 4; k++) {
        float4 v = ((const float4*)src)[base + k * 256];
        uint32_t a, b, c, d;
        split2h(v.x, v.y, a, c);
        split2h(v.z, v.w, b, d);
        ((uint2*)hi)[base + k * 256] = make_uint2(a, b);
        ((uint2*)lo)[base + k * 256] = make_uint2(c, d);
    }
}
__device__ __forceinline__ void cvt4_h(const float* __restrict__ src,
                                       __half* __restrict__ hi, int base)
{
#pragma unroll
    for (int k = 0; k < 4; k++) {
        float4 v = ((const float4*)src)[base + k * 256];
        ((uint2*)hi)[base + k * 256] =
            make_uint2(packh2(v.x, v.y), packh2(v.z, v.w));
    }
}

// ---------------------------------------------------------------------------
// Conversions
// ---------------------------------------------------------------------------
__global__ void __launch_bounds__(256)
cvt_w_kernel(const float* w0, const float* w1, const float* w2, const float* w3,
             const float* w4, const float* w5, const float* w6, const float* w7,
             __half* __restrict__ hi, __half* __restrict__ lo)
{
    const int wi = blockIdx.x >> 8;
    const int ib = (blockIdx.x & 255) * 1024 + threadIdx.x;
    const float* src;
    switch (wi) {
        case 0: src = w0; break;  case 1: src = w1; break;
        case 2: src = w2; break;  case 3: src = w3; break;
        case 4: src = w4; break;  case 5: src = w5; break;
        case 6: src = w6; break;  default: src = w7; break;
    }
    const size_t off = (size_t)wi * (INNER * INNER / 4);
    cvt4_hl(src, (__half*)((uint2*)hi + off), (__half*)((uint2*)lo + off), ib);
}

__global__ void __launch_bounds__(256)
cvt_hsenc_kernel(const float* __restrict__ hs, const float* __restrict__ enc,
                 __half* __restrict__ hs_h,
                 __half* __restrict__ enc_h, __half* __restrict__ enc_l)
{
    const int bx = blockIdx.x;
    if (bx < 2048) {
        cvt4_h(hs, hs_h, bx * 1024 + threadIdx.x);
    } else {
        cvt4_hl(enc, enc_h, enc_l, (bx - 2048) * 1024 + threadIdx.x);
    }
}

// ---------------------------------------------------------------------------
// 3-pass MMA block (pipelined) — for v2 GEMMs (enc, txt-out)
// ---------------------------------------------------------------------------
#define PADK 40
#define MMA_BLOCK_PIPE(acc, abaseh, abasel, bbaseh, bbasel, ks)               \
    {                                                                         \
        uint32_t a0h[4], a1h[4], a0l[4], a1l[4];                              \
        ldsm_x4(a0h, (abaseh) + (ks) * 2);                                    \
        ldsm_x4(a1h, (abaseh) + (ks) * 2 + 16 * PADK * 2);                    \
        ldsm_x4(a0l, (abasel) + (ks) * 2);                                    \
        ldsm_x4(a1l, (abasel) + (ks) * 2 + 16 * PADK * 2);                    \
        uint32_t bh[2][4], bl[4], bln[4];                                     \
        ldsm_x4(bh[0], (bbaseh) + (ks) * 2);                                  \
        ldsm_x4(bl,    (bbasel) + (ks) * 2);                                  \
        _Pragma("unroll")                                                     \
        for (int nbp = 0; nbp < 4; nbp++) {                                   \
            const int c = nbp & 1;                                            \
            mma16816(acc[0][2 * nbp],     a0h, bh[c]);                        \
            mma16816(acc[0][2 * nbp + 1], a0h, bh[c] + 2);                    \
            mma16816(acc[1][2 * nbp],     a1h, bh[c]);                        \
            mma16816(acc[1][2 * nbp + 1], a1h, bh[c] + 2);                    \
            if (nbp < 3)                                                      \
                ldsm_x4(bh[c ^ 1], (bbaseh) + (ks) * 2 +                      \
                        (nbp + 1) * 16 * PADK * 2);                           \
            mma16816(acc[0][2 * nbp],     a0h, bl);                           \
            mma16816(acc[0][2 * nbp + 1], a0h, bl + 2);                       \
            mma16816(acc[1][2 * nbp],     a1h, bl);                           \
            mma16816(acc[1][2 * nbp + 1], a1h, bl + 2);                       \
            if (nbp < 3)                                                      \
                ldsm_x4(bln, (bbasel) + (ks) * 2 +                            \
                        (nbp + 1) * 16 * PADK * 2);                           \
            mma16816(acc[0][2 * nbp],     a0l, bh[c]);                        \
            mma16816(acc[0][2 * nbp + 1], a0l, bh[c] + 2);                    \
            mma16816(acc[1][2 * nbp],     a1l, bh[c]);                        \
            mma16816(acc[1][2 * nbp + 1], a1l, bh[c] + 2);                    \
            if (nbp < 3) {                                                    \
                bl[0] = bln[0]; bl[1] = bln[1];                               \
                bl[2] = bln[2]; bl[3] = bln[3];                               \
            }                                                                 \
        }                                                                     \
    }

// ---------------------------------------------------------------------------
// 2-pass MMA inner loop (A single, W hi/lo) — shared by QKV & vis-out GEMMs
// ---------------------------------------------------------------------------
#define GT_TILE  (128 * PADK)
#define GT_STAGE3 (3 * GT_TILE)
#define QKV_SMEM_BYTES (2 * GT_STAGE3 * 2)

#define MMA_BLOCK_2P(acc, abase, bbaseh, bbasel, ks)                          \
    {                                                                         \
        uint32_t a0[4], a1[4];                                                \
        ldsm_x4(a0, (abase) + (ks) * 2);                                      \
        ldsm_x4(a1, (abase) + (ks) * 2 + 16 * PADK * 2);                      \
        uint32_t bh[2][4], bl[4], bln[4];                                     \
        ldsm_x4(bh[0], (bbaseh) + (ks) * 2);                                  \
        ldsm_x4(bl,    (bbasel) + (ks) * 2);                                  \
        _Pragma("unroll")                                                     \
        for (int nbp = 0; nbp < 4; nbp++) {                                   \
            const int c = nbp & 1;                                            \
            mma16816(acc[0][2 * nbp],     a0, bh[c]);                         \
            mma16816(acc[0][2 * nbp + 1], a0, bh[c] + 2);                     \
            mma16816(acc[1][2 * nbp],     a1, bh[c]);                         \
            mma16816(acc[1][2 * nbp + 1], a1, bh[c] + 2);                     \
            if (nbp < 3)                                                      \
                ldsm_x4(bh[c ^ 1], (bbaseh) + (ks) * 2 +                      \
                        (nbp + 1) * 16 * PADK * 2);                           \
            mma16816(acc[0][2 * nbp],     a0, bl);                            \
            mma16816(acc[0][2 * nbp + 1], a0, bl + 2);                        \
            mma16816(acc[1][2 * nbp],     a1, bl);                            \
            mma16816(acc[1][2 * nbp + 1], a1, bl + 2);                        \
            if (nbp < 3) {                                                    \
                ldsm_x4(bln, (bbasel) + (ks) * 2 + (nbp + 1) * 16 * PADK * 2);\
                bl[0] = bln[0]; bl[1] = bln[1];                               \
                bl[2] = bln[2]; bl[3] = bln[3];                               \
            }                                                                 \
        }                                                                     \
    }

// 2-pass mainloop: 3-tile stage (A, Wh, Wl), 2-stage cp.async pipeline
#define GEMM_2P_MAINLOOP(Ah, Wh, Wl, K, acc)                                  \
    const int rr = t >> 1;                                                    \
    const int cc = (t & 1) * 16;                                              \
    const uint32_t smb = smem_u32(sm);                                        \
    const uint32_t dA = (uint32_t)((rr * PADK + cc) << 1);                    \
    const __half* gA  = Ah + (size_t)(m0 + rr) * K + cc;                      \
    const __half* gWh = Wh + (size_t)(n0 + rr) * K + cc;                      \
    const __half* gWl = Wl + (size_t)(n0 + rr) * K + cc;                      \
    const uint32_t abase_rel = (((wm * 32 + (lane & 15)) * PADK +             \
                                 ((lane >> 4) << 3)) << 1);                   \
    const uint32_t bbase_rel = ((GT_TILE +                                    \
        (wn * 64 + (lane & 7) + ((lane >> 4) << 3)) * PADK +                  \
        (((lane >> 3) & 1) << 3)) << 1);                                      \
    const int NT = K / 32;                                                    \
    {                                                                         \
        const uint32_t sb = smb;                                              \
        CP_ASYNC16(sb + dA,      gA);                                         \
        CP_ASYNC16(sb + dA + 16, gA + 8);                                     \
        CP_ASYNC16(sb + dA + (uint32_t)(GT_TILE << 1),      gWh);             \
        CP_ASYNC16(sb + dA + (uint32_t)(GT_TILE << 1) + 16, gWh + 8);         \
        CP_ASYNC16(sb + dA + (uint32_t)((2 * GT_TILE) << 1),      gWl);       \
        CP_ASYNC16(sb + dA + (uint32_t)((2 * GT_TILE) << 1) + 16, gWl + 8);   \
        CP_COMMIT();                                                          \
    }                                                                         \
    for (int kt = 0; kt < NT; kt++) {                                         \
        const int b = kt & 1;                                                 \
        if (kt + 1 < NT) {                                                    \
            const uint32_t sb = smb +                                         \
                (uint32_t)(((((kt + 1) & 1)) * GT_STAGE3) << 1);              \
            const int ko = (kt + 1) * 32;                                     \
            CP_ASYNC16(sb + dA,      gA + ko);                                \
            CP_ASYNC16(sb + dA + 16, gA + ko + 8);                            \
            CP_ASYNC16(sb + dA + (uint32_t)(GT_TILE << 1),      gWh + ko);    \
            CP_ASYNC16(sb + dA + (uint32_t)(GT_TILE << 1) + 16, gWh + ko + 8);\
            CP_ASYNC16(sb + dA + (uint32_t)((2 * GT_TILE) << 1),      gWl + ko);\
            CP_ASYNC16(sb + dA + (uint32_t)((2 * GT_TILE) << 1) + 16, gWl + ko + 8);\
            CP_COMMIT();                                                      \
            CP_WAIT1();                                                       \
        } else {                                                              \
            CP_WAIT0();                                                       \
        }                                                                     \
        __syncthreads();                                                      \
        const uint32_t stage  = smb + (uint32_t)((b * GT_STAGE3) << 1);       \
        const uint32_t abase  = stage + abase_rel;                            \
        const uint32_t bbaseh = stage + bbase_rel;                            \
        const uint32_t bbasel = bbaseh + (GT_TILE << 1);                      \
        _Pragma("unroll")                                                     \
        for (int ks = 0; ks < 32; ks += 16) {                                 \
            MMA_BLOCK_2P(acc, abase, bbaseh, bbasel, ks)                      \
        }                                                                     \
        __syncthreads();                                                      \
    }

// ---------------------------------------------------------------------------
// vis output projection: 2-pass (A single), fp32 C + bias
// ---------------------------------------------------------------------------
__global__ void __launch_bounds__(256, 2)
gemm_out2_kernel(const __half* __restrict__ Ah,
                 const __half* __restrict__ Wh, const __half* __restrict__ Wl,
                 const float* __restrict__ bias, float* __restrict__ C,
                 int M, int N, int K)
{
    extern __shared__ __half sm[];
    const int t    = threadIdx.x;
    const int lane = t & 31;
    const int wid  = t >> 5;
    const int wm   = wid >> 1;
    const int wn   = wid & 1;
    const int m0   = blockIdx.y * 128;
    const int n0   = blockIdx.x * 128;

    float acc[2][8][4];
#pragma unroll
    for (int i = 0; i < 2; i++)
#pragma unroll
        for (int j = 0; j < 8; j++)
#pragma unroll
            for (int q = 0; q < 4; q++) acc[i][j][q] = 0.f;

    GEMM_2P_MAINLOOP(Ah, Wh, Wl, K, acc)

    const int r0 = m0 + wm * 32 + (lane >> 2);
    const int c0 = n0 + wn * 64 + (lane & 3) * 2;
#pragma unroll
    for (int mi = 0; mi < 2; mi++) {
        const int r = r0 + mi * 16;
#pragma unroll
        for (int nb = 0; nb < 8; nb++) {
            const int c = c0 + nb * 8;
            const float b0 = bias[c], b1 = bias[c + 1];
            *(float2*)(C + (size_t)r * N + c) =
                make_float2(acc[mi][nb][0] + b0, acc[mi][nb][1] + b1);
            *(float2*)(C + (size_t)(r + 8) * N + c) =
                make_float2(acc[mi][nb][2] + b0, acc[mi][nb][3] + b1);
        }
    }
}

// ---------------------------------------------------------------------------
// Fused QKV GEMM: 2-pass, fused RMSNorm + RoPE + scatter epilogue
// ---------------------------------------------------------------------------
__global__ void __launch_bounds__(256, 2)
gemm_qkv_fused_kernel(const __half* __restrict__ Ah,
                      const __half* __restrict__ Wh, const __half* __restrict__ Wl,
                      const float* __restrict__ gq, const float* __restrict__ gk,
                      const float* __restrict__ cosb, const float* __restrict__ sinb,
                      __half* __restrict__ QAh,
                      __half* __restrict__ KAh, __half* __restrict__ KAl,
                      __half* __restrict__ VAh, __half* __restrict__ VAl)
{
    extern __shared__ __half sm[];
    const int t    = threadIdx.x;
    const int lane = t & 31;
    const int wid  = t >> 5;
    const int wm   = wid >> 1;
    const int wn   = wid & 1;
    const int m0   = blockIdx.y * 128;
    const int n0   = blockIdx.x * 128;
    const int K    = INNER;

    float acc[2][8][4];
#pragma unroll
    for (int i = 0; i < 2; i++)
#pragma unroll
        for (int j = 0; j < 8; j++)
#pragma unroll
            for (int q = 0; q < 4; q++) acc[i][j][q] = 0.f;

    GEMM_2P_MAINLOOP(Ah, Wh, Wl, K, acc)

    // ---- fused epilogue ----
    const int nhead = (n0 >> 6) + wn;
    const int sec   = nhead >> 4;
    const int hh    = nhead & 15;
    const int dq    = (lane & 3) * 2;
    const int rbase = m0 + wm * 32 + (lane >> 2);

    const float* gvec = (sec == 0) ? gq : gk;
    const float qscale = (sec == 0) ? ATTN_SCALE : 1.0f;

#pragma unroll
    for (int mi = 0; mi < 2; mi++) {
#pragma unroll
        for (int half = 0; half < 2; half++) {
            const int row = rbase + mi * 16 + half * 8;
            const int vi = half * 2;
            const int j = row & 7, tt = row >> 3;
            const size_t dstb = (((size_t)(j * NUM_HEADS + hh)) * STOT + tt) * HEAD_DIM;

            if (sec == 2) {
                uint32_t* oh32 = (uint32_t*)(VAh + dstb);
                uint32_t* ol32 = (uint32_t*)(VAl + dstb);
#pragma unroll
                for (int nb = 0; nb < 8; nb++) {
                    uint32_t hi, lo;
                    split2h(acc[mi][nb][vi], acc[mi][nb][vi + 1], hi, lo);
                    const int d = dq + nb * 8;
                    oh32[d >> 1] = hi;
                    ol32[d >> 1] = lo;
                }
            } else {
                float ss = 0.f;
#pragma unroll
                for (int nb = 0; nb < 8; nb++) {
                    ss += acc[mi][nb][vi] * acc[mi][nb][vi];
                    ss += acc[mi][nb][vi + 1] * acc[mi][nb][vi + 1];
                }
                ss += __shfl_xor_sync(0xffffffffu, ss, 1);
                ss += __shfl_xor_sync(0xffffffffu, ss, 2);
                const float rms = rsqrtf(ss * (1.f / HEAD_DIM) + EPS_RMS);

                const float* cb = cosb + (size_t)row * HEAD_DIM;
                const float* sb = sinb + (size_t)row * HEAD_DIM;
#pragma unroll
                for (int nb = 0; nb < 4; nb++) {
                    const int d0 = dq + nb * 8;
                    const int d1 = d0 + 32;
                    const float x00 = acc[mi][nb][vi]         * rms * gvec[d0];
                    const float x01 = acc[mi][nb][vi + 1]     * rms * gvec[d0 + 1];
                    const float x10 = acc[mi][nb + 4][vi]     * rms * gvec[d1];
                    const float x11 = acc[mi][nb + 4][vi + 1] * rms * gvec[d1 + 1];
                    const float y00 = (x00 * cb[d0]     - x10 * sb[d0])     * qscale;
                    const float y01 = (x01 * cb[d0 + 1] - x11 * sb[d0 + 1]) * qscale;
                    const float y10 = (x10 * cb[d1]     + x00 * sb[d1])     * qscale;
                    const float y11 = (x11 * cb[d1 + 1] + x01 * sb[d1 + 1]) * qscale;
                    if (sec == 0) {
                        uint32_t* oh32 = (uint32_t*)(QAh + dstb);
                        oh32[d0 >> 1] = packh2(y00, y01);
                        oh32[d1 >> 1] = packh2(y10, y11);
                    } else {
                        uint32_t* oh32 = (uint32_t*)(KAh + dstb);
                        uint32_t* ol32 = (uint32_t*)(KAl + dstb);
                        uint32_t hi, lo;
                        split2h(y00, y01, hi, lo);
                        oh32[d0 >> 1] = hi;  ol32[d0 >> 1] = lo;
                        split2h(y10, y11, hi, lo);
                        oh32[d1 >> 1] = hi;  ol32[d1 >> 1] = lo;
                    }
                }
            }
        }
    }
}

// ---------------------------------------------------------------------------
// GEMM v2: 3-pass, 256x128 CTA, 512 threads, 3-stage, K-split (small-M GEMMs)
// ---------------------------------------------------------------------------
#define V2_TILE_A (256 * PADK)
#define V2_TILE_W (128 * PADK)
#define V2_STAGE (2 * V2_TILE_A + 2 * V2_TILE_W)
#define GEMM2_SMEM_BYTES (3 * V2_STAGE * 2)

__global__ void __launch_bounds__(512, 1)
gemm_v2_kernel(const __half* __restrict__ Ah, const __half* __restrict__ Al,
               const __half* __restrict__ Wh, const __half* __restrict__ Wl,
               float* __restrict__ C, int M, int N, int K, int kparts)
{
    extern __shared__ __half sm[];
    const int t    = threadIdx.x;
    const int lane = t & 31;
    const int wid  = t >> 5;
    const int wm   = wid >> 1;
    const int wn   = wid & 1;
    const int m0   = blockIdx.y * 256;
    const int n0   = blockIdx.x * 128;

    const int KC    = K / kparts;
    const int kbase = blockIdx.z * KC;
    const int NT    = KC / 32;

    float acc[2][8][4];
#pragma unroll
    for (int i = 0; i < 2; i++)
#pragma unroll
        for (int j = 0; j < 8; j++)
#pragma unroll
            for (int q = 0; q < 4; q++) acc[i][j][q] = 0.f;

    const int rr = t >> 2;
    const int cc = (t & 3) * 8;
    const uint32_t smb = smem_u32(sm);

    const __half* pA0 = Ah + (size_t)(m0 + rr)       * K + kbase + cc;
    const __half* pA1 = Ah + (size_t)(m0 + rr + 128) * K + kbase + cc;
    const __half* pL0 = Al + (size_t)(m0 + rr)       * K + kbase + cc;
    const __half* pL1 = Al + (size_t)(m0 + rr + 128) * K + kbase + cc;
    const __half* pWh = Wh + (size_t)(n0 + rr)       * K + kbase + cc;
    const __half* pWl = Wl + (size_t)(n0 + rr)       * K + kbase + cc;

    const uint32_t dA0 = (uint32_t)((rr * PADK + cc) << 1);
    const uint32_t dA1 = (uint32_t)(((rr + 128) * PADK + cc) << 1);
    const uint32_t dL0 = dA0 + (uint32_t)(V2_TILE_A << 1);
    const uint32_t dL1 = dA1 + (uint32_t)(V2_TILE_A << 1);
    const uint32_t dWh = dA0 + (uint32_t)((2 * V2_TILE_A) << 1);
    const uint32_t dWl = dA0 + (uint32_t)(((2 * V2_TILE_A) + V2_TILE_W) << 1);

#define V2_LOAD(kt, stg) do {                                              \
    const uint32_t sb = smb + (uint32_t)(((stg) * V2_STAGE) << 1);         \
    const int ko = (kt) * 32;                                              \
    CP_ASYNC16(sb + dA0, pA0 + ko);                                        \
    CP_ASYNC16(sb + dA1, pA1 + ko);                                        \
    CP_ASYNC16(sb + dL0, pL0 + ko);                                        \
    CP_ASYNC16(sb + dL1, pL1 + ko);                                        \
    CP_ASYNC16(sb + dWh, pWh + ko);                                        \
    CP_ASYNC16(sb + dWl, pWl + ko);                                        \
    CP_COMMIT();                                                           \
} while (0)

    V2_LOAD(0, 0);
    V2_LOAD(1, 1);

    const uint32_t abase_rel = (uint32_t)((((wm * 32 + (lane & 15)) * PADK +
                                            ((lane >> 4) << 3))) << 1);
    const uint32_t bbase_rel = (uint32_t)(((2 * V2_TILE_A +
                     (wn * 64 + (lane & 7) + ((lane >> 4) << 3)) * PADK +
                     (((lane >> 3) & 1) << 3))) << 1);

    int stg = 0;
    for (int kt = 0; kt < NT; kt++) {
        if (kt + 2 < NT) {
            const int ps = (stg + 2 >= 3) ? (stg - 1) : (stg + 2);
            V2_LOAD(kt + 2, ps);
            CP_WAIT2();
        } else {
            CP_WAIT0();
        }
        __syncthreads();

        const uint32_t stage  = smb + (uint32_t)((stg * V2_STAGE) << 1);
        const uint32_t abaseh = stage + abase_rel;
        const uint32_t abasel = abaseh + (uint32_t)(V2_TILE_A << 1);
        const uint32_t bbaseh = stage + bbase_rel;
        const uint32_t bbasel = bbaseh + (uint32_t)(V2_TILE_W << 1);

#pragma unroll
        for (int ks = 0; ks < 32; ks += 16) {
            MMA_BLOCK_PIPE(acc, abaseh, abasel, bbaseh, bbasel, ks)
        }
        __syncthreads();
        stg = (stg + 1 >= 3) ? 0 : (stg + 1);
    }

    float* Cz = C + (size_t)blockIdx.z * M * N;
    const int r0 = m0 + wm * 32 + (lane >> 2);
    const int c0 = n0 + wn * 64 + (lane & 3) * 2;
#pragma unroll
    for (int mi = 0; mi < 2; mi++) {
        const int r = r0 + mi * 16;
#pragma unroll
        for (int nb = 0; nb < 8; nb++) {
            const int c = c0 + nb * 8;
            *(float2*)(Cz + (size_t)r * N + c) =
                make_float2(acc[mi][nb][0], acc[mi][nb][1]);
            *(float2*)(Cz + (size_t)(r + 8) * N + c) =
                make_float2(acc[mi][nb][2], acc[mi][nb][3]);
        }
    }
}

// ---------------------------------------------------------------------------
// K-split reduce (with bias)
// ---------------------------------------------------------------------------
__global__ void __launch_bounds__(256)
reduce4_kernel(const float* __restrict__ part, const float* __restrict__ bias,
               float* __restrict__ out, int MN, int N)
{
    const int i = blockIdx.x * 256 + threadIdx.x;
    if (i * 4 >= MN) return;
    const int q = MN / 4;
    float4 a = ((const float4*)part)[i];
    float4 b = ((const float4*)part)[i + q];
    float4 c = ((const float4*)part)[i + 2 * q];
    float4 d = ((const float4*)part)[i + 3 * q];
    float4 r = make_float4(a.x + b.x + c.x + d.x, a.y + b.y + c.y + d.y,
                           a.z + b.z + c.z + d.z, a.w + b.w + c.w + d.w);
    if (bias) {
        const int col = (i * 4) % N;
        r.x += bias[col];  r.y += bias[col + 1];
        r.z += bias[col + 2];  r.w += bias[col + 3];
    }
    ((float4*)out)[i] = r;
}

// ---------------------------------------------------------------------------
// RMSNorm + broadcast scatter (text): Q hi-only, K/V hi+lo
// ---------------------------------------------------------------------------
__global__ void __launch_bounds__(256)
enc_post_kernel(const float* __restrict__ part,
                const float* __restrict__ gaq, const float* __restrict__ gak,
                __half* __restrict__ QAh,
                __half* __restrict__ KAh, __half* __restrict__ KAl,
                __half* __restrict__ VAh, __half* __restrict__ VAl)
{
    const int warp = (blockIdx.x * blockDim.x + threadIdx.x) >> 5;
    const int lane = threadIdx.x & 31;
    const int tt = warp >> 4;
    const int h  = warp & 15;
    if (tt >= T_LEN) return;

    const size_t src = (size_t)tt * INNER3 + h * HEAD_DIM;
    const size_t PQ = (size_t)T_LEN * INNER3;
    float a0 = 0.f, a1 = 0.f, b0 = 0.f, b1 = 0.f, v0 = 0.f, v1 = 0.f;
#pragma unroll
    for (int z = 0; z < 4; z++) {
        const float* p = part + z * PQ + src;
        a0 += p[lane];              a1 += p[lane + 32];
        b0 += p[INNER + lane];      b1 += p[INNER + lane + 32];
        v0 += p[2*INNER + lane];    v1 += p[2*INNER + lane + 32];
    }

    float ra = rsqrtf(warp_sum32(a0 * a0 + a1 * a1) * (1.f / HEAD_DIM) + EPS_RMS);
    float rb = rsqrtf(warp_sum32(b0 * b0 + b1 * b1) * (1.f / HEAD_DIM) + EPS_RMS);

    a0 *= ra * gaq[lane] * ATTN_SCALE;  a1 *= ra * gaq[lane + 32] * ATTN_SCALE;
    b0 *= rb * gak[lane];               b1 *= rb * gak[lane + 32];

#pragma unroll
    for (int j = 0; j < SPARSE_N; j++) {
        const size_t dst =
            (((size_t)(j * NUM_HEADS + h)) * STOT + G_LEN + tt) * HEAD_DIM;
        QAh[dst + lane]      = __float2half_rn(a0);
        QAh[dst + lane + 32] = __float2half_rn(a1);
        store_splith(KAh, KAl, dst + lane,      b0);
        store_splith(KAh, KAl, dst + lane + 32, b1);
        store_splith(VAh, VAl, dst + lane,      v0);
        store_splith(VAh, VAl, dst + lane + 32, v1);
    }
}

// ---------------------------------------------------------------------------
// Flash attention fp16x2: Q single, K/V hi/lo; static-max softmax;
// fused vis gather (vis_h single). BQ=256, 512 threads.
// ---------------------------------------------------------------------------
#define APAD 72
#define AQ_ELEMS (256 * APAD)
#define KV_TILE  (64 * APAD)
#define KV_STAGE (4 * KV_TILE)
#define ATT_SM_BYTES ((AQ_ELEMS + 2 * KV_STAGE) * 2)

__global__ void __launch_bounds__(512, 1)
attn_mma_kernel(const __half* __restrict__ Qhg,
                const __half* __restrict__ Khg, const __half* __restrict__ Klg,
                const __half* __restrict__ Vhg, const __half* __restrict__ Vlg,
                float* __restrict__ OA, __half* __restrict__ vis_h)
{
    extern __shared__ __half smA[];
    const int t    = threadIdx.x;
    const int lane = t & 31;
    const int w    = t >> 5;
    const int jh   = blockIdx.y;
    const int q0   = blockIdx.x * 256;
    const size_t base = (size_t)jh * STOT * HEAD_DIM;

    const uint32_t smb = smem_u32(smA);

    const int tile = t >> 7;
    const int l128 = t & 127;
    const int krr  = l128 >> 3;
    const int kcc  = (l128 & 7) * 8;
    const __half* kvsrc =
        (tile == 0) ? Khg : (tile == 1) ? Klg : (tile == 2) ? Vhg : Vlg;
    const uint32_t kvdst0 = smb + ((AQ_ELEMS + tile * KV_TILE + krr * APAD + kcc) << 1);

    {
        const __half* g = kvsrc + base + (size_t)krr * 64 + kcc;
#pragma unroll
        for (int i = 0; i < 4; i++)
            CP_ASYNC16(kvdst0 + (uint32_t)((i * 16 * APAD) << 1),
                       g + (size_t)(i * 16) * 64);
        CP_COMMIT();
    }

    {
        const int row = t >> 1, c0 = (t & 1) * 32;
        const __half* gh = Qhg + base + (size_t)(q0 + row) * 64 + c0;
        __half* sh = smA + row * APAD + c0;
#pragma unroll
        for (int c = 0; c < 32; c += 8)
            *(uint4*)(sh + c) = *(const uint4*)(gh + c);
    }

    float o[8][4];
#pragma unroll
    for (int i = 0; i < 8; i++)
#pragma unroll
        for (int j = 0; j < 4; j++) o[i][j] = 0.f;
    float l0r = 0.f, l1r = 0.f;

    const uint32_t qfrag = smb + (((w * 16 + (lane & 15)) * APAD + ((lane >> 4) << 3)) << 1);
    const uint32_t kfrag_rel = ((((lane & 7) + ((lane >> 4) << 3)) * APAD + (((lane >> 3) & 1) << 3)) << 1);
    const uint32_t vfrag_rel = (((2 * KV_TILE) + ((lane & 7) + (((lane >> 3) & 1) << 3)) * APAD + ((lane >> 4) << 3)) << 1);

    for (int kt = 0; kt < 20; kt++) {
        const int b = kt & 1;
        if (kt + 1 < 20) {
            const __half* g = kvsrc + base + (size_t)((kt + 1) * 64 + krr) * 64 + kcc;
            const uint32_t d = kvdst0 + (uint32_t)((((kt + 1) & 1) * KV_STAGE) << 1);
#pragma unroll
            for (int i = 0; i < 4; i++)
                CP_ASYNC16(d + (uint32_t)((i * 16 * APAD) << 1),
                           g + (size_t)(i * 16) * 64);
            CP_COMMIT();
            CP_WAIT1();
        } else {
            CP_WAIT0();
        }
        __syncthreads();

        const uint32_t kvstage = smb + (uint32_t)(((AQ_ELEMS + b * KV_STAGE)) << 1);
        const uint32_t kfragh = kvstage + kfrag_rel;
        const uint32_t kfragl = kfragh + (KV_TILE << 1);
        const uint32_t vfrag  = kvstage + vfrag_rel;

        float s[8][4];
#pragma unroll
        for (int i = 0; i < 8; i++)
#pragma unroll
            for (int j = 0; j < 4; j++) s[i][j] = 0.f;

        // ---- scores: q_h * (k_h + k_l), 2 passes ----
#pragma unroll
        for (int ks = 0; ks < 64; ks += 16) {
            uint32_t ah[4];
            ldsm_x4(ah, qfrag + ks * 2);
            uint32_t kh[2][4], kl[4], kln[4];
            ldsm_x4(kh[0], kfragh + ks * 2);
            ldsm_x4(kl,    kfragl + ks * 2);
#pragma unroll
            for (int nbp = 0; nbp < 4; nbp++) {
                const int c = nbp & 1;
                mma16816(s[2 * nbp],     ah, kh[c]);
                mma16816(s[2 * nbp + 1], ah, kh[c] + 2);
                if (nbp < 3)
                    ldsm_x4(kh[c ^ 1], kfragh + ks * 2 + (nbp + 1) * 16 * APAD * 2);
                mma16816(s[2 * nbp],     ah, kl);
                mma16816(s[2 * nbp + 1], ah, kl + 2);
                if (nbp < 3) {
                    ldsm_x4(kln, kfragl + ks * 2 + (nbp + 1) * 16 * APAD * 2);
                    kl[0] = kln[0]; kl[1] = kln[1];
                    kl[2] = kln[2]; kl[3] = kln[3];
                }
            }
        }

        // ---- static-max softmax ----
        float rs0 = 0.f, rs1 = 0.f;
#pragma unroll
        for (int nb = 0; nb < 8; nb++) {
            s[nb][0] = __expf(s[nb][0] - SMAX);  rs0 += s[nb][0];
            s[nb][1] = __expf(s[nb][1] - SMAX);  rs0 += s[nb][1];
            s[nb][2] = __expf(s[nb][2] - SMAX);  rs1 += s[nb][2];
            s[nb][3] = __expf(s[nb][3] - SMAX);  rs1 += s[nb][3];
        }
        rs0 += __shfl_xor_sync(0xffffffffu, rs0, 1);
        rs0 += __shfl_xor_sync(0xffffffffu, rs0, 2);
        rs1 += __shfl_xor_sync(0xffffffffu, rs1, 1);
        rs1 += __shfl_xor_sync(0xffffffffu, rs1, 2);
        l0r += rs0;
        l1r += rs1;

        // ---- PV: p_h * (v_h + v_l), 2 passes ----
#pragma unroll
        for (int kb2 = 0; kb2 < 4; kb2++) {
            uint32_t ph[4];
            ph[0] = packh2(s[2 * kb2][0],     s[2 * kb2][1]);
            ph[1] = packh2(s[2 * kb2][2],     s[2 * kb2][3]);
            ph[2] = packh2(s[2 * kb2 + 1][0], s[2 * kb2 + 1][1]);
            ph[3] = packh2(s[2 * kb2 + 1][2], s[2 * kb2 + 1][3]);
            const uint32_t vb = vfrag + kb2 * 16 * APAD * 2;
            uint32_t vh[2][4], vl[4], vln[4];
            ldsm_x4_t(vh[0], vb);
            ldsm_x4_t(vl, vb + (KV_TILE << 1));
#pragma unroll
            for (int dbp = 0; dbp < 4; dbp++) {
                const int c = dbp & 1;
                mma16816(o[2 * dbp],     ph, vh[c]);
                mma16816(o[2 * dbp + 1], ph, vh[c] + 2);
                if (dbp < 3)
                    ldsm_x4_t(vh[c ^ 1], vb + (dbp + 1) * 16 * 2);
                mma16816(o[2 * dbp],     ph, vl);
                mma16816(o[2 * dbp + 1], ph, vl + 2);
                if (dbp < 3) {
                    ldsm_x4_t(vln, vb + (KV_TILE << 1) + (dbp + 1) * 16 * 2);
                    vl[0] = vln[0]; vl[1] = vln[1];
                    vl[2] = vln[2]; vl[3] = vln[3];
                }
            }
        }
        __syncthreads();
    }

    const float inv0 = 1.f / l0r, inv1 = 1.f / l1r;
    const int row = q0 + w * 16 + (lane >> 2);
    const int col = (lane & 3) * 2;
    if (blockIdx.x < 4) {
        const int j = jh >> 4, h = jh & 15;
        uint32_t* vh32 = (uint32_t*)vis_h;
        const size_t b0 = ((size_t)row * 8 + j) * INNER + h * 64;
        const size_t b1 = ((size_t)(row + 8) * 8 + j) * INNER + h * 64;
#pragma unroll
        for (int db = 0; db < 8; db++) {
            vh32[(b0 + db * 8 + col) >> 1] = packh2(o[db][0] * inv0, o[db][1] * inv0);
            vh32[(b1 + db * 8 + col) >> 1] = packh2(o[db][2] * inv1, o[db][3] * inv1);
        }
    } else {
#pragma unroll
        for (int db = 0; db < 8; db++) {
            *(float2*)(OA + base + (size_t)row * 64 + db * 8 + col) =
                make_float2(o[db][0] * inv0, o[db][1] * inv0);
            *(float2*)(OA + base + (size_t)(row + 8) * 64 + db * 8 + col) =
                make_float2(o[db][2] * inv1, o[db][3] * inv1);
        }
    }
}

// ---------------------------------------------------------------------------
// Gather text rows -> fp16 hi/lo (mean over j)
// ---------------------------------------------------------------------------
__global__ void __launch_bounds__(256)
gather_txt_kernel(const float* __restrict__ OA,
                  __half* __restrict__ th, __half* __restrict__ tl)
{
    const int i = blockIdx.x * 256 + threadIdx.x;
    const int idx = i * 4;
    const int tt = idx >> 10, e = idx & 1023;
    const int h = e >> 6, d = e & 63;
    float4 acc = make_float4(0.f, 0.f, 0.f, 0.f);
#pragma unroll
    for (int j = 0; j < SPARSE_N; j++) {
        float4 v = *(const float4*)(OA +
            (((size_t)(j * NUM_HEADS + h)) * STOT + G_LEN + tt) * HEAD_DIM + d);
        acc.x += v.x; acc.y += v.y; acc.z += v.z; acc.w += v.w;
    }
    acc.x *= 0.125f; acc.y *= 0.125f; acc.z *= 0.125f; acc.w *= 0.125f;
    uint32_t h01, l01, h23, l23;
    split2h(acc.x, acc.y, h01, l01);
    split2h(acc.z, acc.w, h23, l23);
    ((uint2*)th)[i] = make_uint2(h01, h23);
    ((uint2*)tl)[i] = make_uint2(l01, l23);
}

// ---------------------------------------------------------------------------
// kernel_launch
// ---------------------------------------------------------------------------
extern "C" void kernel_launch(void* const* d_in, const int* in_sizes, int n_in,
                              void* d_out, int out_size)
{
    const float* hs   = (const float*)d_in[0];
    const float* enc  = (const float*)d_in[1];
    const float* bout  = (const float*)d_in[9];
    const float* baout = (const float*)d_in[11];
    const float* gq   = (const float*)d_in[12];
    const float* gk   = (const float*)d_in[13];
    const float* gaq  = (const float*)d_in[14];
    const float* gak  = (const float*)d_in[15];
    const float* rc   = (const float*)d_in[16];
    const float* rs   = (const float*)d_in[17];
    float* out = (float*)d_out;

    float *encpart, *txtpart, *OA;
    __half *hs_h, *enc_h, *enc_l, *w_h, *w_l;
    __half *vis_h, *txt_h, *txt_l;
    __half *QAh, *KAh, *KAl, *VAh, *VAl;
    cudaGetSymbolAddress((void**)&encpart, g_encpart);
    cudaGetSymbolAddress((void**)&txtpart, g_txtpart);
    cudaGetSymbolAddress((void**)&OA,    g_OA);
    cudaGetSymbolAddress((void**)&hs_h,  g_hs_h);
    cudaGetSymbolAddress((void**)&enc_h, g_enc_h);
    cudaGetSymbolAddress((void**)&enc_l, g_enc_l);
    cudaGetSymbolAddress((void**)&w_h,   g_w_h);
    cudaGetSymbolAddress((void**)&w_l,   g_w_l);
    cudaGetSymbolAddress((void**)&vis_h, g_vis_h);
    cudaGetSymbolAddress((void**)&txt_h, g_txt_h);
    cudaGetSymbolAddress((void**)&txt_l, g_txt_l);
    cudaGetSymbolAddress((void**)&QAh,   g_QAh);
    cudaGetSymbolAddress((void**)&KAh,   g_KAh);
    cudaGetSymbolAddress((void**)&KAl,   g_KAl);
    cudaGetSymbolAddress((void**)&VAh,   g_VAh);
    cudaGetSymbolAddress((void**)&VAl,   g_VAl);

    cudaFuncSetAttribute(gemm_out2_kernel,
                         cudaFuncAttributeMaxDynamicSharedMemorySize, QKV_SMEM_BYTES);
    cudaFuncSetAttribute(gemm_qkv_fused_kernel,
                         cudaFuncAttributeMaxDynamicSharedMemorySize, QKV_SMEM_BYTES);
    cudaFuncSetAttribute(gemm_v2_kernel,
                         cudaFuncAttributeMaxDynamicSharedMemorySize, GEMM2_SMEM_BYTES);
    cudaFuncSetAttribute(attn_mma_kernel,
                         cudaFuncAttributeMaxDynamicSharedMemorySize, ATT_SM_BYTES);

    const size_t WS = (size_t)INNER * INNER;

    // [0] weight conversions, [1] hs+enc conversions
    cvt_w_kernel<<<2048, 256>>>(
        (const float*)d_in[2], (const float*)d_in[3], (const float*)d_in[4],
        (const float*)d_in[5], (const float*)d_in[6], (const float*)d_in[7],
        (const float*)d_in[8], (const float*)d_in[10], w_h, w_l);
    cvt_hsenc_kernel<<<2112, 256>>>(hs, enc, hs_h, enc_h, enc_l);

    // [2] enc QKV GEMM (3-pass v2, K-split x4), [3] enc post (fused reduce)
    gemm_v2_kernel<<<dim3(INNER3 / 128, 1, 4), 512, GEMM2_SMEM_BYTES>>>(
        enc_h, enc_l, w_h + 3 * WS, w_l + 3 * WS, encpart, T_LEN, INNER3, INNER, 4);
    enc_post_kernel<<<(T_LEN * NUM_HEADS) / 8, 256>>>(
        encpart, gaq, gak, QAh, KAh, KAl, VAh, VAl);

    // [4] big QKV GEMM (2-pass fp16, fused epilogue)
    gemm_qkv_fused_kernel<<<dim3(INNER3 / 128, S_LEN / 128), 256, QKV_SMEM_BYTES>>>(
        hs_h, w_h + 0 * WS, w_l + 0 * WS,
        gq, gk, rc, rs, QAh, KAh, KAl, VAh, VAl);

    // [5] attention (2-pass fp16, static-max softmax, fused vis gather)
    attn_mma_kernel<<<dim3(STOT / 256, NJH), 512, ATT_SM_BYTES>>>(
        QAh, KAh, KAl, VAh, VAl, OA, vis_h);

    // [6] text gather
    gather_txt_kernel<<<(T_LEN * INNER / 4) / 256, 256>>>(OA, txt_h, txt_l);

    // [7] vis out GEMM (2-pass, A single)
    gemm_out2_kernel<<<dim3(INNER / 128, S_LEN / 128), 256, QKV_SMEM_BYTES>>>(
        vis_h, w_h + 6 * WS, w_l + 6 * WS, bout, out, S_LEN, INNER, INNER);

    // [8] txt out GEMM (3-pass v2, K-split x4), [9] reduce with bias
    gemm_v2_kernel<<<dim3(INNER / 128, 1, 4), 512, GEMM2_SMEM_BYTES>>>(
        txt_h, txt_l, w_h + 7 * WS, w_l + 7 * WS, txtpart, T_LEN, INNER, INNER, 4);
    reduce4_kernel<<<(T_LEN * INNER / 4) / 256, 256>>>(
        txtpart, baout, out + (size_t)S_LEN * INNER, T_LEN * INNER, INNER);
}

// round 15
// speedup vs baseline: 1.3355x; 1.0363x over previous
#include <cuda_runtime.h>
#include <cuda_fp16.h>
#include <math.h>
#include <stdint.h>

// ---------------------------------------------------------------------------
// Problem constants
// ---------------------------------------------------------------------------
#define S_LEN     8192
#define T_LEN     256
#define NUM_HEADS 16
#define HEAD_DIM  64
#define INNER     1024
#define INNER3    3072
#define SPARSE_N  8
#define G_LEN     1024
#define STOT      1280
#define NJH       128
#define EPS_RMS   1e-5f
#define ATTN_SCALE 0.125f
#define SMAX      8.0f
#define ATT_ELEMS (NJH * STOT * HEAD_DIM)

// ---------------------------------------------------------------------------
// Static device scratch
// ---------------------------------------------------------------------------
__device__ float g_encpart[4 * T_LEN * INNER3];
__device__ float g_txtpart[4 * T_LEN * INNER];
__device__ float g_OA[ATT_ELEMS];

__device__ __half g_hs_h[S_LEN * INNER];
__device__ __half g_enc_h[T_LEN * INNER];
__device__ __half g_enc_l[T_LEN * INNER];
__device__ __half g_w_h[8 * INNER * INNER];
__device__ __half g_w_l[8 * INNER * INNER];
__device__ __half g_vis_h[S_LEN * INNER];
__device__ __half g_txt_h[T_LEN * INNER];
__device__ __half g_txt_l[T_LEN * INNER];
__device__ __half g_QAh[ATT_ELEMS];
__device__ __half g_KAh[ATT_ELEMS];
__device__ __half g_KAl[ATT_ELEMS];
__device__ __half g_VAh[ATT_ELEMS];
__device__ __half g_VAl[ATT_ELEMS];

// ---------------------------------------------------------------------------
// Helpers
// ---------------------------------------------------------------------------
__device__ __forceinline__ uint32_t smem_u32(const void* p) {
    uint32_t a;
    asm("{ .reg .u64 t; cvta.to.shared.u64 t, %1; cvt.u32.u64 %0, t; }"
        : "=r"(a) : "l"(p));
    return a;
}

#define CP_ASYNC16(dst, src) \
    asm volatile("cp.async.cg.shared.global [%0], [%1], 16;" :: "r"(dst), "l"(src))
#define CP_COMMIT() asm volatile("cp.async.commit_group;" ::: "memory")
#define CP_WAIT0()  asm volatile("cp.async.wait_group 0;" ::: "memory")
#define CP_WAIT1()  asm volatile("cp.async.wait_group 1;" ::: "memory")
#define CP_WAIT2()  asm volatile("cp.async.wait_group 2;" ::: "memory")

__device__ __forceinline__ void ldsm_x4(uint32_t* r, uint32_t a) {
    asm volatile("ldmatrix.sync.aligned.m8n8.x4.shared.b16 {%0,%1,%2,%3}, [%4];"
        : "=r"(r[0]), "=r"(r[1]), "=r"(r[2]), "=r"(r[3]) : "r"(a));
}
__device__ __forceinline__ void ldsm_x4_t(uint32_t* r, uint32_t a) {
    asm volatile("ldmatrix.sync.aligned.m8n8.x4.trans.shared.b16 {%0,%1,%2,%3}, [%4];"
        : "=r"(r[0]), "=r"(r[1]), "=r"(r[2]), "=r"(r[3]) : "r"(a));
}
__device__ __forceinline__ void mma16816(float* c, const uint32_t* a, const uint32_t* b) {
    asm volatile(
        "mma.sync.aligned.m16n8k16.row.col.f32.f16.f16.f32 "
        "{%0,%1,%2,%3}, {%4,%5,%6,%7}, {%8,%9}, {%0,%1,%2,%3};"
        : "+f"(c[0]), "+f"(c[1]), "+f"(c[2]), "+f"(c[3])
        : "r"(a[0]), "r"(a[1]), "r"(a[2]), "r"(a[3]), "r"(b[0]), "r"(b[1]));
}

__device__ __forceinline__ uint32_t packh2(float x, float y) {
    __half2 h = __floats2half2_rn(x, y);
    return *reinterpret_cast<uint32_t*>(&h);
}
__device__ __forceinline__ void split2h(float x, float y, uint32_t& hi, uint32_t& lo) {
    __half hx = __float2half_rn(x), hy = __float2half_rn(y);
    hi = ((uint32_t)__half_as_ushort(hx)) | ((uint32_t)__half_as_ushort(hy) << 16);
    lo = packh2(x - __half2float(hx), y - __half2float(hy));
}
__device__ __forceinline__ void store_splith(__half* ph, __half* pl,
                                             size_t idx, float v) {
    __half h = __float2half_rn(v);
    ph[idx] = h;
    pl[idx] = __float2half_rn(v - __half2float(h));
}
__device__ __forceinline__ float warp_sum32(float v) {
#pragma unroll
    for (int o = 16; o > 0; o >>= 1)
        v += __shfl_xor_sync(0xffffffffu, v, o);
    return v;
}

__device__ __forceinline__ void cvt4_hl(const float* __restrict__ src,
                                        __half* __restrict__ hi,
                                        __half* __restrict__ lo, int base)
{
#pragma unroll
    for (int k = 0; k < 4; k++) {
        float4 v = ((const float4*)src)[base + k * 256];
        uint32_t a, b, c, d;
        split2h(v.x, v.y, a, c);
        split2h(v.z, v.w, b, d);
        ((uint2*)hi)[base + k * 256] = make_uint2(a, b);
        ((uint2*)lo)[base + k * 256] = make_uint2(c, d);
    }
}
__device__ __forceinline__ void cvt4_h(const float* __restrict__ src,
                                       __half* __restrict__ hi, int base)
{
#pragma unroll
    for (int k = 0; k < 4; k++) {
        float4 v = ((const float4*)src)[base + k * 256];
        ((uint2*)hi)[base + k * 256] =
            make_uint2(packh2(v.x, v.y), packh2(v.z, v.w));
    }
}

// ---------------------------------------------------------------------------
// One merged conversion launch:
// blocks [0,2048): weights (hi/lo); [2048,4096): hs (hi only); [4096,4160): enc
// ---------------------------------------------------------------------------
__global__ void __launch_bounds__(256)
cvt_all_kernel(const float* w0, const float* w1, const float* w2, const float* w3,
               const float* w4, const float* w5, const float* w6, const float* w7,
               const float* __restrict__ hs, const float* __restrict__ enc,
               __half* __restrict__ w_h, __half* __restrict__ w_l,
               __half* __restrict__ hs_h,
               __half* __restrict__ enc_h, __half* __restrict__ enc_l)
{
    const int bx = blockIdx.x;
    if (bx < 2048) {
        const int wi = bx >> 8;
        const int ib = (bx & 255) * 1024 + threadIdx.x;
        const float* src;
        switch (wi) {
            case 0: src = w0; break;  case 1: src = w1; break;
            case 2: src = w2; break;  case 3: src = w3; break;
            case 4: src = w4; break;  case 5: src = w5; break;
            case 6: src = w6; break;  default: src = w7; break;
        }
        const size_t off = (size_t)wi * (INNER * INNER / 4);
        cvt4_hl(src, (__half*)((uint2*)w_h + off), (__half*)((uint2*)w_l + off), ib);
    } else if (bx < 4096) {
        cvt4_h(hs, hs_h, (bx - 2048) * 1024 + threadIdx.x);
    } else {
        cvt4_hl(enc, enc_h, enc_l, (bx - 4096) * 1024 + threadIdx.x);
    }
}

// ---------------------------------------------------------------------------
// 3-pass MMA block (pipelined) — for v2 GEMMs (enc, txt-out)
// ---------------------------------------------------------------------------
#define PADK 40
#define MMA_BLOCK_PIPE(acc, abaseh, abasel, bbaseh, bbasel, ks)               \
    {                                                                         \
        uint32_t a0h[4], a1h[4], a0l[4], a1l[4];                              \
        ldsm_x4(a0h, (abaseh) + (ks) * 2);                                    \
        ldsm_x4(a1h, (abaseh) + (ks) * 2 + 16 * PADK * 2);                    \
        ldsm_x4(a0l, (abasel) + (ks) * 2);                                    \
        ldsm_x4(a1l, (abasel) + (ks) * 2 + 16 * PADK * 2);                    \
        uint32_t bh[2][4], bl[4], bln[4];                                     \
        ldsm_x4(bh[0], (bbaseh) + (ks) * 2);                                  \
        ldsm_x4(bl,    (bbasel) + (ks) * 2);                                  \
        _Pragma("unroll")                                                     \
        for (int nbp = 0; nbp < 4; nbp++) {                                   \
            const int c = nbp & 1;                                            \
            mma16816(acc[0][2 * nbp],     a0h, bh[c]);                        \
            mma16816(acc[0][2 * nbp + 1], a0h, bh[c] + 2);                    \
            mma16816(acc[1][2 * nbp],     a1h, bh[c]);                        \
            mma16816(acc[1][2 * nbp + 1], a1h, bh[c] + 2);                    \
            if (nbp < 3)                                                      \
                ldsm_x4(bh[c ^ 1], (bbaseh) + (ks) * 2 +                      \
                        (nbp + 1) * 16 * PADK * 2);                           \
            mma16816(acc[0][2 * nbp],     a0h, bl);                           \
            mma16816(acc[0][2 * nbp + 1], a0h, bl + 2);                       \
            mma16816(acc[1][2 * nbp],     a1h, bl);                           \
            mma16816(acc[1][2 * nbp + 1], a1h, bl + 2);                       \
            if (nbp < 3)                                                      \
                ldsm_x4(bln, (bbasel) + (ks) * 2 +                            \
                        (nbp + 1) * 16 * PADK * 2);                           \
            mma16816(acc[0][2 * nbp],     a0l, bh[c]);                        \
            mma16816(acc[0][2 * nbp + 1], a0l, bh[c] + 2);                    \
            mma16816(acc[1][2 * nbp],     a1l, bh[c]);                        \
            mma16816(acc[1][2 * nbp + 1], a1l, bh[c] + 2);                    \
            if (nbp < 3) {                                                    \
                bl[0] = bln[0]; bl[1] = bln[1];                               \
                bl[2] = bln[2]; bl[3] = bln[3];                               \
            }                                                                 \
        }                                                                     \
    }

// ---------------------------------------------------------------------------
// 2-pass MMA inner loop (A single, W hi/lo)
// ---------------------------------------------------------------------------
#define GT_TILE  (128 * PADK)
#define GT_STAGE3 (3 * GT_TILE)
#define QKV_SMEM_BYTES (2 * GT_STAGE3 * 2)

#define MMA_BLOCK_2P(acc, abase, bbaseh, bbasel, ks)                          \
    {                                                                         \
        uint32_t a0[4], a1[4];                                                \
        ldsm_x4(a0, (abase) + (ks) * 2);                                      \
        ldsm_x4(a1, (abase) + (ks) * 2 + 16 * PADK * 2);                      \
        uint32_t bh[2][4], bl[4], bln[4];                                     \
        ldsm_x4(bh[0], (bbaseh) + (ks) * 2);                                  \
        ldsm_x4(bl,    (bbasel) + (ks) * 2);                                  \
        _Pragma("unroll")                                                     \
        for (int nbp = 0; nbp < 4; nbp++) {                                   \
            const int c = nbp & 1;                                            \
            mma16816(acc[0][2 * nbp],     a0, bh[c]);                         \
            mma16816(acc[0][2 * nbp + 1], a0, bh[c] + 2);                     \
            mma16816(acc[1][2 * nbp],     a1, bh[c]);                         \
            mma16816(acc[1][2 * nbp + 1], a1, bh[c] + 2);                     \
            if (nbp < 3)                                                      \
                ldsm_x4(bh[c ^ 1], (bbaseh) + (ks) * 2 +                      \
                        (nbp + 1) * 16 * PADK * 2);                           \
            mma16816(acc[0][2 * nbp],     a0, bl);                            \
            mma16816(acc[0][2 * nbp + 1], a0, bl + 2);                        \
            mma16816(acc[1][2 * nbp],     a1, bl);                            \
            mma16816(acc[1][2 * nbp + 1], a1, bl + 2);                        \
            if (nbp < 3) {                                                    \
                ldsm_x4(bln, (bbasel) + (ks) * 2 + (nbp + 1) * 16 * PADK * 2);\
                bl[0] = bln[0]; bl[1] = bln[1];                               \
                bl[2] = bln[2]; bl[3] = bln[3];                               \
            }                                                                 \
        }                                                                     \
    }

#define GEMM_2P_MAINLOOP(Ah, Wh, Wl, K, acc)                                  \
    const int rr = t >> 1;                                                    \
    const int cc = (t & 1) * 16;                                              \
    const uint32_t smb = smem_u32(sm);                                        \
    const uint32_t dA = (uint32_t)((rr * PADK + cc) << 1);                    \
    const __half* gA  = Ah + (size_t)(m0 + rr) * K + cc;                      \
    const __half* gWh = Wh + (size_t)(n0 + rr) * K + cc;                      \
    const __half* gWl = Wl + (size_t)(n0 + rr) * K + cc;                      \
    const uint32_t abase_rel = (((wm * 32 + (lane & 15)) * PADK +             \
                                 ((lane >> 4) << 3)) << 1);                   \
    const uint32_t bbase_rel = ((GT_TILE +                                    \
        (wn * 64 + (lane & 7) + ((lane >> 4) << 3)) * PADK +                  \
        (((lane >> 3) & 1) << 3)) << 1);                                      \
    const int NT = K / 32;                                                    \
    {                                                                         \
        const uint32_t sb = smb;                                              \
        CP_ASYNC16(sb + dA,      gA);                                         \
        CP_ASYNC16(sb + dA + 16, gA + 8);                                     \
        CP_ASYNC16(sb + dA + (uint32_t)(GT_TILE << 1),      gWh);             \
        CP_ASYNC16(sb + dA + (uint32_t)(GT_TILE << 1) + 16, gWh + 8);         \
        CP_ASYNC16(sb + dA + (uint32_t)((2 * GT_TILE) << 1),      gWl);       \
        CP_ASYNC16(sb + dA + (uint32_t)((2 * GT_TILE) << 1) + 16, gWl + 8);   \
        CP_COMMIT();                                                          \
    }                                                                         \
    for (int kt = 0; kt < NT; kt++) {                                         \
        const int b = kt & 1;                                                 \
        if (kt + 1 < NT) {                                                    \
            const uint32_t sb = smb +                                         \
                (uint32_t)(((((kt + 1) & 1)) * GT_STAGE3) << 1);              \
            const int ko = (kt + 1) * 32;                                     \
            CP_ASYNC16(sb + dA,      gA + ko);                                \
            CP_ASYNC16(sb + dA + 16, gA + ko + 8);                            \
            CP_ASYNC16(sb + dA + (uint32_t)(GT_TILE << 1),      gWh + ko);    \
            CP_ASYNC16(sb + dA + (uint32_t)(GT_TILE << 1) + 16, gWh + ko + 8);\
            CP_ASYNC16(sb + dA + (uint32_t)((2 * GT_TILE) << 1),      gWl + ko);\
            CP_ASYNC16(sb + dA + (uint32_t)((2 * GT_TILE) << 1) + 16, gWl + ko + 8);\
            CP_COMMIT();                                                      \
            CP_WAIT1();                                                       \
        } else {                                                              \
            CP_WAIT0();                                                       \
        }                                                                     \
        __syncthreads();                                                      \
        const uint32_t stage  = smb + (uint32_t)((b * GT_STAGE3) << 1);       \
        const uint32_t abase  = stage + abase_rel;                            \
        const uint32_t bbaseh = stage + bbase_rel;                            \
        const uint32_t bbasel = bbaseh + (GT_TILE << 1);                      \
        _Pragma("unroll")                                                     \
        for (int ks = 0; ks < 32; ks += 16) {                                 \
            MMA_BLOCK_2P(acc, abase, bbaseh, bbasel, ks)                      \
        }                                                                     \
        __syncthreads();                                                      \
    }

// ---------------------------------------------------------------------------
// vis output projection: 2-pass (A single), fp32 C + bias
// ---------------------------------------------------------------------------
__global__ void __launch_bounds__(256, 2)
gemm_out2_kernel(const __half* __restrict__ Ah,
                 const __half* __restrict__ Wh, const __half* __restrict__ Wl,
                 const float* __restrict__ bias, float* __restrict__ C,
                 int M, int N, int K)
{
    extern __shared__ __half sm[];
    const int t    = threadIdx.x;
    const int lane = t & 31;
    const int wid  = t >> 5;
    const int wm   = wid >> 1;
    const int wn   = wid & 1;
    const int m0   = blockIdx.y * 128;
    const int n0   = blockIdx.x * 128;

    float acc[2][8][4];
#pragma unroll
    for (int i = 0; i < 2; i++)
#pragma unroll
        for (int j = 0; j < 8; j++)
#pragma unroll
            for (int q = 0; q < 4; q++) acc[i][j][q] = 0.f;

    GEMM_2P_MAINLOOP(Ah, Wh, Wl, K, acc)

    const int r0 = m0 + wm * 32 + (lane >> 2);
    const int c0 = n0 + wn * 64 + (lane & 3) * 2;
#pragma unroll
    for (int mi = 0; mi < 2; mi++) {
        const int r = r0 + mi * 16;
#pragma unroll
        for (int nb = 0; nb < 8; nb++) {
            const int c = c0 + nb * 8;
            const float b0 = bias[c], b1 = bias[c + 1];
            *(float2*)(C + (size_t)r * N + c) =
                make_float2(acc[mi][nb][0] + b0, acc[mi][nb][1] + b1);
            *(float2*)(C + (size_t)(r + 8) * N + c) =
                make_float2(acc[mi][nb][2] + b0, acc[mi][nb][3] + b1);
        }
    }
}

// ---------------------------------------------------------------------------
// Fused QKV GEMM: 2-pass, fused RMSNorm + RoPE + scatter epilogue
// ---------------------------------------------------------------------------
__global__ void __launch_bounds__(256, 2)
gemm_qkv_fused_kernel(const __half* __restrict__ Ah,
                      const __half* __restrict__ Wh, const __half* __restrict__ Wl,
                      const float* __restrict__ gq, const float* __restrict__ gk,
                      const float* __restrict__ cosb, const float* __restrict__ sinb,
                      __half* __restrict__ QAh,
                      __half* __restrict__ KAh, __half* __restrict__ KAl,
                      __half* __restrict__ VAh, __half* __restrict__ VAl)
{
    extern __shared__ __half sm[];
    const int t    = threadIdx.x;
    const int lane = t & 31;
    const int wid  = t >> 5;
    const int wm   = wid >> 1;
    const int wn   = wid & 1;
    const int m0   = blockIdx.y * 128;
    const int n0   = blockIdx.x * 128;
    const int K    = INNER;

    float acc[2][8][4];
#pragma unroll
    for (int i = 0; i < 2; i++)
#pragma unroll
        for (int j = 0; j < 8; j++)
#pragma unroll
            for (int q = 0; q < 4; q++) acc[i][j][q] = 0.f;

    GEMM_2P_MAINLOOP(Ah, Wh, Wl, K, acc)

    // ---- fused epilogue ----
    const int nhead = (n0 >> 6) + wn;
    const int sec   = nhead >> 4;
    const int hh    = nhead & 15;
    const int dq    = (lane & 3) * 2;
    const int rbase = m0 + wm * 32 + (lane >> 2);

    const float* gvec = (sec == 0) ? gq : gk;
    const float qscale = (sec == 0) ? ATTN_SCALE : 1.0f;

#pragma unroll
    for (int mi = 0; mi < 2; mi++) {
#pragma unroll
        for (int half = 0; half < 2; half++) {
            const int row = rbase + mi * 16 + half * 8;
            const int vi = half * 2;
            const int j = row & 7, tt = row >> 3;
            const size_t dstb = (((size_t)(j * NUM_HEADS + hh)) * STOT + tt) * HEAD_DIM;

            if (sec == 2) {
                uint32_t* oh32 = (uint32_t*)(VAh + dstb);
                uint32_t* ol32 = (uint32_t*)(VAl + dstb);
#pragma unroll
                for (int nb = 0; nb < 8; nb++) {
                    uint32_t hi, lo;
                    split2h(acc[mi][nb][vi], acc[mi][nb][vi + 1], hi, lo);
                    const int d = dq + nb * 8;
                    oh32[d >> 1] = hi;
                    ol32[d >> 1] = lo;
                }
            } else {
                float ss = 0.f;
#pragma unroll
                for (int nb = 0; nb < 8; nb++) {
                    ss += acc[mi][nb][vi] * acc[mi][nb][vi];
                    ss += acc[mi][nb][vi + 1] * acc[mi][nb][vi + 1];
                }
                ss += __shfl_xor_sync(0xffffffffu, ss, 1);
                ss += __shfl_xor_sync(0xffffffffu, ss, 2);
                const float rms = rsqrtf(ss * (1.f / HEAD_DIM) + EPS_RMS);

                const float* cb = cosb + (size_t)row * HEAD_DIM;
                const float* sb = sinb + (size_t)row * HEAD_DIM;
#pragma unroll
                for (int nb = 0; nb < 4; nb++) {
                    const int d0 = dq + nb * 8;
                    const int d1 = d0 + 32;
                    const float x00 = acc[mi][nb][vi]         * rms * gvec[d0];
                    const float x01 = acc[mi][nb][vi + 1]     * rms * gvec[d0 + 1];
                    const float x10 = acc[mi][nb + 4][vi]     * rms * gvec[d1];
                    const float x11 = acc[mi][nb + 4][vi + 1] * rms * gvec[d1 + 1];
                    const float y00 = (x00 * cb[d0]     - x10 * sb[d0])     * qscale;
                    const float y01 = (x01 * cb[d0 + 1] - x11 * sb[d0 + 1]) * qscale;
                    const float y10 = (x10 * cb[d1]     + x00 * sb[d1])     * qscale;
                    const float y11 = (x11 * cb[d1 + 1] + x01 * sb[d1 + 1]) * qscale;
                    if (sec == 0) {
                        uint32_t* oh32 = (uint32_t*)(QAh + dstb);
                        oh32[d0 >> 1] = packh2(y00, y01);
                        oh32[d1 >> 1] = packh2(y10, y11);
                    } else {
                        uint32_t* oh32 = (uint32_t*)(KAh + dstb);
                        uint32_t* ol32 = (uint32_t*)(KAl + dstb);
                        uint32_t hi, lo;
                        split2h(y00, y01, hi, lo);
                        oh32[d0 >> 1] = hi;  ol32[d0 >> 1] = lo;
                        split2h(y10, y11, hi, lo);
                        oh32[d1 >> 1] = hi;  ol32[d1 >> 1] = lo;
                    }
                }
            }
        }
    }
}

// ---------------------------------------------------------------------------
// GEMM v2: 3-pass, 256x128 CTA, 512 threads, 3-stage, K-split (small-M GEMMs)
// ---------------------------------------------------------------------------
#define V2_TILE_A (256 * PADK)
#define V2_TILE_W (128 * PADK)
#define V2_STAGE (2 * V2_TILE_A + 2 * V2_TILE_W)
#define GEMM2_SMEM_BYTES (3 * V2_STAGE * 2)

__global__ void __launch_bounds__(512, 1)
gemm_v2_kernel(const __half* __restrict__ Ah, const __half* __restrict__ Al,
               const __half* __restrict__ Wh, const __half* __restrict__ Wl,
               float* __restrict__ C, int M, int N, int K, int kparts)
{
    extern __shared__ __half sm[];
    const int t    = threadIdx.x;
    const int lane = t & 31;
    const int wid  = t >> 5;
    const int wm   = wid >> 1;
    const int wn   = wid & 1;
    const int m0   = blockIdx.y * 256;
    const int n0   = blockIdx.x * 128;

    const int KC    = K / kparts;
    const int kbase = blockIdx.z * KC;
    const int NT    = KC / 32;

    float acc[2][8][4];
#pragma unroll
    for (int i = 0; i < 2; i++)
#pragma unroll
        for (int j = 0; j < 8; j++)
#pragma unroll
            for (int q = 0; q < 4; q++) acc[i][j][q] = 0.f;

    const int rr = t >> 2;
    const int cc = (t & 3) * 8;
    const uint32_t smb = smem_u32(sm);

    const __half* pA0 = Ah + (size_t)(m0 + rr)       * K + kbase + cc;
    const __half* pA1 = Ah + (size_t)(m0 + rr + 128) * K + kbase + cc;
    const __half* pL0 = Al + (size_t)(m0 + rr)       * K + kbase + cc;
    const __half* pL1 = Al + (size_t)(m0 + rr + 128) * K + kbase + cc;
    const __half* pWh = Wh + (size_t)(n0 + rr)       * K + kbase + cc;
    const __half* pWl = Wl + (size_t)(n0 + rr)       * K + kbase + cc;

    const uint32_t dA0 = (uint32_t)((rr * PADK + cc) << 1);
    const uint32_t dA1 = (uint32_t)(((rr + 128) * PADK + cc) << 1);
    const uint32_t dL0 = dA0 + (uint32_t)(V2_TILE_A << 1);
    const uint32_t dL1 = dA1 + (uint32_t)(V2_TILE_A << 1);
    const uint32_t dWh = dA0 + (uint32_t)((2 * V2_TILE_A) << 1);
    const uint32_t dWl = dA0 + (uint32_t)(((2 * V2_TILE_A) + V2_TILE_W) << 1);

#define V2_LOAD(kt, stg) do {                                              \
    const uint32_t sb = smb + (uint32_t)(((stg) * V2_STAGE) << 1);         \
    const int ko = (kt) * 32;                                              \
    CP_ASYNC16(sb + dA0, pA0 + ko);                                        \
    CP_ASYNC16(sb + dA1, pA1 + ko);                                        \
    CP_ASYNC16(sb + dL0, pL0 + ko);                                        \
    CP_ASYNC16(sb + dL1, pL1 + ko);                                        \
    CP_ASYNC16(sb + dWh, pWh + ko);                                        \
    CP_ASYNC16(sb + dWl, pWl + ko);                                        \
    CP_COMMIT();                                                           \
} while (0)

    V2_LOAD(0, 0);
    V2_LOAD(1, 1);

    const uint32_t abase_rel = (uint32_t)((((wm * 32 + (lane & 15)) * PADK +
                                            ((lane >> 4) << 3))) << 1);
    const uint32_t bbase_rel = (uint32_t)(((2 * V2_TILE_A +
                     (wn * 64 + (lane & 7) + ((lane >> 4) << 3)) * PADK +
                     (((lane >> 3) & 1) << 3))) << 1);

    int stg = 0;
    for (int kt = 0; kt < NT; kt++) {
        if (kt + 2 < NT) {
            const int ps = (stg + 2 >= 3) ? (stg - 1) : (stg + 2);
            V2_LOAD(kt + 2, ps);
            CP_WAIT2();
        } else {
            CP_WAIT0();
        }
        __syncthreads();

        const uint32_t stage  = smb + (uint32_t)((stg * V2_STAGE) << 1);
        const uint32_t abaseh = stage + abase_rel;
        const uint32_t abasel = abaseh + (uint32_t)(V2_TILE_A << 1);
        const uint32_t bbaseh = stage + bbase_rel;
        const uint32_t bbasel = bbaseh + (uint32_t)(V2_TILE_W << 1);

#pragma unroll
        for (int ks = 0; ks < 32; ks += 16) {
            MMA_BLOCK_PIPE(acc, abaseh, abasel, bbaseh, bbasel, ks)
        }
        __syncthreads();
        stg = (stg + 1 >= 3) ? 0 : (stg + 1);
    }

    float* Cz = C + (size_t)blockIdx.z * M * N;
    const int r0 = m0 + wm * 32 + (lane >> 2);
    const int c0 = n0 + wn * 64 + (lane & 3) * 2;
#pragma unroll
    for (int mi = 0; mi < 2; mi++) {
        const int r = r0 + mi * 16;
#pragma unroll
        for (int nb = 0; nb < 8; nb++) {
            const int c = c0 + nb * 8;
            *(float2*)(Cz + (size_t)r * N + c) =
                make_float2(acc[mi][nb][0], acc[mi][nb][1]);
            *(float2*)(Cz + (size_t)(r + 8) * N + c) =
                make_float2(acc[mi][nb][2], acc[mi][nb][3]);
        }
    }
}

// ---------------------------------------------------------------------------
// K-split reduce (with bias)
// ---------------------------------------------------------------------------
__global__ void __launch_bounds__(256)
reduce4_kernel(const float* __restrict__ part, const float* __restrict__ bias,
               float* __restrict__ out, int MN, int N)
{
    const int i = blockIdx.x * 256 + threadIdx.x;
    if (i * 4 >= MN) return;
    const int q = MN / 4;
    float4 a = ((const float4*)part)[i];
    float4 b = ((const float4*)part)[i + q];
    float4 c = ((const float4*)part)[i + 2 * q];
    float4 d = ((const float4*)part)[i + 3 * q];
    float4 r = make_float4(a.x + b.x + c.x + d.x, a.y + b.y + c.y + d.y,
                           a.z + b.z + c.z + d.z, a.w + b.w + c.w + d.w);
    if (bias) {
        const int col = (i * 4) % N;
        r.x += bias[col];  r.y += bias[col + 1];
        r.z += bias[col + 2];  r.w += bias[col + 3];
    }
    ((float4*)out)[i] = r;
}

// ---------------------------------------------------------------------------
// RMSNorm + broadcast scatter (text): Q hi-only, K/V hi+lo
// ---------------------------------------------------------------------------
__global__ void __launch_bounds__(256)
enc_post_kernel(const float* __restrict__ part,
                const float* __restrict__ gaq, const float* __restrict__ gak,
                __half* __restrict__ QAh,
                __half* __restrict__ KAh, __half* __restrict__ KAl,
                __half* __restrict__ VAh, __half* __restrict__ VAl)
{
    const int warp = (blockIdx.x * blockDim.x + threadIdx.x) >> 5;
    const int lane = threadIdx.x & 31;
    const int tt = warp >> 4;
    const int h  = warp & 15;
    if (tt >= T_LEN) return;

    const size_t src = (size_t)tt * INNER3 + h * HEAD_DIM;
    const size_t PQ = (size_t)T_LEN * INNER3;
    float a0 = 0.f, a1 = 0.f, b0 = 0.f, b1 = 0.f, v0 = 0.f, v1 = 0.f;
#pragma unroll
    for (int z = 0; z < 4; z++) {
        const float* p = part + z * PQ + src;
        a0 += p[lane];              a1 += p[lane + 32];
        b0 += p[INNER + lane];      b1 += p[INNER + lane + 32];
        v0 += p[2*INNER + lane];    v1 += p[2*INNER + lane + 32];
    }

    float ra = rsqrtf(warp_sum32(a0 * a0 + a1 * a1) * (1.f / HEAD_DIM) + EPS_RMS);
    float rb = rsqrtf(warp_sum32(b0 * b0 + b1 * b1) * (1.f / HEAD_DIM) + EPS_RMS);

    a0 *= ra * gaq[lane] * ATTN_SCALE;  a1 *= ra * gaq[lane + 32] * ATTN_SCALE;
    b0 *= rb * gak[lane];               b1 *= rb * gak[lane + 32];

#pragma unroll
    for (int j = 0; j < SPARSE_N; j++) {
        const size_t dst =
            (((size_t)(j * NUM_HEADS + h)) * STOT + G_LEN + tt) * HEAD_DIM;
        QAh[dst + lane]      = __float2half_rn(a0);
        QAh[dst + lane + 32] = __float2half_rn(a1);
        store_splith(KAh, KAl, dst + lane,      b0);
        store_splith(KAh, KAl, dst + lane + 32, b1);
        store_splith(VAh, VAl, dst + lane,      v0);
        store_splith(VAh, VAl, dst + lane + 32, v1);
    }
}

// ---------------------------------------------------------------------------
// Flash attention fp16x2: BQ=128, 256 threads, 2 CTAs/SM.
// Q single, K/V hi/lo; static-max softmax; fused vis gather.
// ---------------------------------------------------------------------------
#define APAD 72
#define AQ_ELEMS (128 * APAD)
#define KV_TILE  (64 * APAD)
#define KV_STAGE (4 * KV_TILE)
#define ATT_SM_BYTES ((AQ_ELEMS + 2 * KV_STAGE) * 2)   // 92160

__global__ void __launch_bounds__(256, 2)
attn_mma_kernel(const __half* __restrict__ Qhg,
                const __half* __restrict__ Khg, const __half* __restrict__ Klg,
                const __half* __restrict__ Vhg, const __half* __restrict__ Vlg,
                float* __restrict__ OA, __half* __restrict__ vis_h)
{
    extern __shared__ __half smA[];
    const int t    = threadIdx.x;
    const int lane = t & 31;
    const int w    = t >> 5;
    const int jh   = blockIdx.y;
    const int q0   = blockIdx.x * 128;
    const size_t base = (size_t)jh * STOT * HEAD_DIM;

    const uint32_t smb = smem_u32(smA);

    // KV loader: tile = t>>6 (0:Kh 1:Kl 2:Vh 3:Vl), 64 threads/tile, 8 chunks
    const int tile = t >> 6;
    const int l64  = t & 63;
    const int krr  = l64 >> 3;           // 0..7
    const int kcc  = (l64 & 7) * 8;
    const __half* kvsrc =
        (tile == 0) ? Khg : (tile == 1) ? Klg : (tile == 2) ? Vhg : Vlg;
    const uint32_t kvdst0 = smb + ((AQ_ELEMS + tile * KV_TILE + krr * APAD + kcc) << 1);

    {
        const __half* g = kvsrc + base + (size_t)krr * 64 + kcc;
#pragma unroll
        for (int i = 0; i < 8; i++)
            CP_ASYNC16(kvdst0 + (uint32_t)((i * 8 * APAD) << 1),
                       g + (size_t)(i * 8) * 64);
        CP_COMMIT();
    }

    // Q tile 128x64 fp16
    {
        const int row = t >> 1, c0 = (t & 1) * 32;
        const __half* gh = Qhg + base + (size_t)(q0 + row) * 64 + c0;
        __half* sh = smA + row * APAD + c0;
#pragma unroll
        for (int c = 0; c < 32; c += 8)
            *(uint4*)(sh + c) = *(const uint4*)(gh + c);
    }

    float o[8][4];
#pragma unroll
    for (int i = 0; i < 8; i++)
#pragma unroll
        for (int j = 0; j < 4; j++) o[i][j] = 0.f;
    float l0r = 0.f, l1r = 0.f;

    const uint32_t qfrag = smb + (((w * 16 + (lane & 15)) * APAD + ((lane >> 4) << 3)) << 1);
    const uint32_t kfrag_rel = ((((lane & 7) + ((lane >> 4) << 3)) * APAD + (((lane >> 3) & 1) << 3)) << 1);
    const uint32_t vfrag_rel = (((2 * KV_TILE) + ((lane & 7) + (((lane >> 3) & 1) << 3)) * APAD + ((lane >> 4) << 3)) << 1);

    for (int kt = 0; kt < 20; kt++) {
        const int b = kt & 1;
        if (kt + 1 < 20) {
            const __half* g = kvsrc + base + (size_t)((kt + 1) * 64 + krr) * 64 + kcc;
            const uint32_t d = kvdst0 + (uint32_t)((((kt + 1) & 1) * KV_STAGE) << 1);
#pragma unroll
            for (int i = 0; i < 8; i++)
                CP_ASYNC16(d + (uint32_t)((i * 8 * APAD) << 1),
                           g + (size_t)(i * 8) * 64);
            CP_COMMIT();
            CP_WAIT1();
        } else {
            CP_WAIT0();
        }
        __syncthreads();

        const uint32_t kvstage = smb + (uint32_t)(((AQ_ELEMS + b * KV_STAGE)) << 1);
        const uint32_t kfragh = kvstage + kfrag_rel;
        const uint32_t kfragl = kfragh + (KV_TILE << 1);
        const uint32_t vfrag  = kvstage + vfrag_rel;

        float s[8][4];
#pragma unroll
        for (int i = 0; i < 8; i++)
#pragma unroll
            for (int j = 0; j < 4; j++) s[i][j] = 0.f;

        // ---- scores: q_h * (k_h + k_l), 2 passes ----
#pragma unroll
        for (int ks = 0; ks < 64; ks += 16) {
            uint32_t ah[4];
            ldsm_x4(ah, qfrag + ks * 2);
            uint32_t kh[2][4], kl[4], kln[4];
            ldsm_x4(kh[0], kfragh + ks * 2);
            ldsm_x4(kl,    kfragl + ks * 2);
#pragma unroll
            for (int nbp = 0; nbp < 4; nbp++) {
                const int c = nbp & 1;
                mma16816(s[2 * nbp],     ah, kh[c]);
                mma16816(s[2 * nbp + 1], ah, kh[c] + 2);
                if (nbp < 3)
                    ldsm_x4(kh[c ^ 1], kfragh + ks * 2 + (nbp + 1) * 16 * APAD * 2);
                mma16816(s[2 * nbp],     ah, kl);
                mma16816(s[2 * nbp + 1], ah, kl + 2);
                if (nbp < 3) {
                    ldsm_x4(kln, kfragl + ks * 2 + (nbp + 1) * 16 * APAD * 2);
                    kl[0] = kln[0]; kl[1] = kln[1];
                    kl[2] = kln[2]; kl[3] = kln[3];
                }
            }
        }

        // ---- static-max softmax ----
        float rs0 = 0.f, rs1 = 0.f;
#pragma unroll
        for (int nb = 0; nb < 8; nb++) {
            s[nb][0] = __expf(s[nb][0] - SMAX);  rs0 += s[nb][0];
            s[nb][1] = __expf(s[nb][1] - SMAX);  rs0 += s[nb][1];
            s[nb][2] = __expf(s[nb][2] - SMAX);  rs1 += s[nb][2];
            s[nb][3] = __expf(s[nb][3] - SMAX);  rs1 += s[nb][3];
        }
        rs0 += __shfl_xor_sync(0xffffffffu, rs0, 1);
        rs0 += __shfl_xor_sync(0xffffffffu, rs0, 2);
        rs1 += __shfl_xor_sync(0xffffffffu, rs1, 1);
        rs1 += __shfl_xor_sync(0xffffffffu, rs1, 2);
        l0r += rs0;
        l1r += rs1;

        // ---- PV: p_h * (v_h + v_l), 2 passes ----
#pragma unroll
        for (int kb2 = 0; kb2 < 4; kb2++) {
            uint32_t ph[4];
            ph[0] = packh2(s[2 * kb2][0],     s[2 * kb2][1]);
            ph[1] = packh2(s[2 * kb2][2],     s[2 * kb2][3]);
            ph[2] = packh2(s[2 * kb2 + 1][0], s[2 * kb2 + 1][1]);
            ph[3] = packh2(s[2 * kb2 + 1][2], s[2 * kb2 + 1][3]);
            const uint32_t vb = vfrag + kb2 * 16 * APAD * 2;
            uint32_t vh[2][4], vl[4], vln[4];
            ldsm_x4_t(vh[0], vb);
            ldsm_x4_t(vl, vb + (KV_TILE << 1));
#pragma unroll
            for (int dbp = 0; dbp < 4; dbp++) {
                const int c = dbp & 1;
                mma16816(o[2 * dbp],     ph, vh[c]);
                mma16816(o[2 * dbp + 1], ph, vh[c] + 2);
                if (dbp < 3)
                    ldsm_x4_t(vh[c ^ 1], vb + (dbp + 1) * 16 * 2);
                mma16816(o[2 * dbp],     ph, vl);
                mma16816(o[2 * dbp + 1], ph, vl + 2);
                if (dbp < 3) {
                    ldsm_x4_t(vln, vb + (KV_TILE << 1) + (dbp + 1) * 16 * 2);
                    vl[0] = vln[0]; vl[1] = vln[1];
                    vl[2] = vln[2]; vl[3] = vln[3];
                }
            }
        }
        __syncthreads();
    }

    const float inv0 = 1.f / l0r, inv1 = 1.f / l1r;
    const int row = q0 + w * 16 + (lane >> 2);
    const int col = (lane & 3) * 2;
    if (blockIdx.x < 8) {
        const int j = jh >> 4, h = jh & 15;
        uint32_t* vh32 = (uint32_t*)vis_h;
        const size_t b0 = ((size_t)row * 8 + j) * INNER + h * 64;
        const size_t b1 = ((size_t)(row + 8) * 8 + j) * INNER + h * 64;
#pragma unroll
        for (int db = 0; db < 8; db++) {
            vh32[(b0 + db * 8 + col) >> 1] = packh2(o[db][0] * inv0, o[db][1] * inv0);
            vh32[(b1 + db * 8 + col) >> 1] = packh2(o[db][2] * inv1, o[db][3] * inv1);
        }
    } else {
#pragma unroll
        for (int db = 0; db < 8; db++) {
            *(float2*)(OA + base + (size_t)row * 64 + db * 8 + col) =
                make_float2(o[db][0] * inv0, o[db][1] * inv0);
            *(float2*)(OA + base + (size_t)(row + 8) * 64 + db * 8 + col) =
                make_float2(o[db][2] * inv1, o[db][3] * inv1);
        }
    }
}

// ---------------------------------------------------------------------------
// Gather text rows -> fp16 hi/lo (mean over j)
// ---------------------------------------------------------------------------
__global__ void __launch_bounds__(256)
gather_txt_kernel(const float* __restrict__ OA,
                  __half* __restrict__ th, __half* __restrict__ tl)
{
    const int i = blockIdx.x * 256 + threadIdx.x;
    const int idx = i * 4;
    const int tt = idx >> 10, e = idx & 1023;
    const int h = e >> 6, d = e & 63;
    float4 acc = make_float4(0.f, 0.f, 0.f, 0.f);
#pragma unroll
    for (int j = 0; j < SPARSE_N; j++) {
        float4 v = *(const float4*)(OA +
            (((size_t)(j * NUM_HEADS + h)) * STOT + G_LEN + tt) * HEAD_DIM + d);
        acc.x += v.x; acc.y += v.y; acc.z += v.z; acc.w += v.w;
    }
    acc.x *= 0.125f; acc.y *= 0.125f; acc.z *= 0.125f; acc.w *= 0.125f;
    uint32_t h01, l01, h23, l23;
    split2h(acc.x, acc.y, h01, l01);
    split2h(acc.z, acc.w, h23, l23);
    ((uint2*)th)[i] = make_uint2(h01, h23);
    ((uint2*)tl)[i] = make_uint2(l01, l23);
}

// ---------------------------------------------------------------------------
// kernel_launch
// ---------------------------------------------------------------------------
extern "C" void kernel_launch(void* const* d_in, const int* in_sizes, int n_in,
                              void* d_out, int out_size)
{
    const float* hs   = (const float*)d_in[0];
    const float* enc  = (const float*)d_in[1];
    const float* bout  = (const float*)d_in[9];
    const float* baout = (const float*)d_in[11];
    const float* gq   = (const float*)d_in[12];
    const float* gk   = (const float*)d_in[13];
    const float* gaq  = (const float*)d_in[14];
    const float* gak  = (const float*)d_in[15];
    const float* rc   = (const float*)d_in[16];
    const float* rs   = (const float*)d_in[17];
    float* out = (float*)d_out;

    float *encpart, *txtpart, *OA;
    __half *hs_h, *enc_h, *enc_l, *w_h, *w_l;
    __half *vis_h, *txt_h, *txt_l;
    __half *QAh, *KAh, *KAl, *VAh, *VAl;
    cudaGetSymbolAddress((void**)&encpart, g_encpart);
    cudaGetSymbolAddress((void**)&txtpart, g_txtpart);
    cudaGetSymbolAddress((void**)&OA,    g_OA);
    cudaGetSymbolAddress((void**)&hs_h,  g_hs_h);
    cudaGetSymbolAddress((void**)&enc_h, g_enc_h);
    cudaGetSymbolAddress((void**)&enc_l, g_enc_l);
    cudaGetSymbolAddress((void**)&w_h,   g_w_h);
    cudaGetSymbolAddress((void**)&w_l,   g_w_l);
    cudaGetSymbolAddress((void**)&vis_h, g_vis_h);
    cudaGetSymbolAddress((void**)&txt_h, g_txt_h);
    cudaGetSymbolAddress((void**)&txt_l, g_txt_l);
    cudaGetSymbolAddress((void**)&QAh,   g_QAh);
    cudaGetSymbolAddress((void**)&KAh,   g_KAh);
    cudaGetSymbolAddress((void**)&KAl,   g_KAl);
    cudaGetSymbolAddress((void**)&VAh,   g_VAh);
    cudaGetSymbolAddress((void**)&VAl,   g_VAl);

    cudaFuncSetAttribute(gemm_out2_kernel,
                         cudaFuncAttributeMaxDynamicSharedMemorySize, QKV_SMEM_BYTES);
    cudaFuncSetAttribute(gemm_qkv_fused_kernel,
                         cudaFuncAttributeMaxDynamicSharedMemorySize, QKV_SMEM_BYTES);
    cudaFuncSetAttribute(gemm_v2_kernel,
                         cudaFuncAttributeMaxDynamicSharedMemorySize, GEMM2_SMEM_BYTES);
    cudaFuncSetAttribute(attn_mma_kernel,
                         cudaFuncAttributeMaxDynamicSharedMemorySize, ATT_SM_BYTES);

    const size_t WS = (size_t)INNER * INNER;

    // [0] all conversions (weights hi/lo + hs hi + enc hi/lo), one launch
    cvt_all_kernel<<<4160, 256>>>(
        (const float*)d_in[2], (const float*)d_in[3], (const float*)d_in[4],
        (const float*)d_in[5], (const float*)d_in[6], (const float*)d_in[7],
        (const float*)d_in[8], (const float*)d_in[10], hs, enc,
        w_h, w_l, hs_h, enc_h, enc_l);

    // [1] enc QKV GEMM (3-pass v2, K-split x4), [2] enc post (fused reduce)
    gemm_v2_kernel<<<dim3(INNER3 / 128, 1, 4), 512, GEMM2_SMEM_BYTES>>>(
        enc_h, enc_l, w_h + 3 * WS, w_l + 3 * WS, encpart, T_LEN, INNER3, INNER, 4);
    enc_post_kernel<<<(T_LEN * NUM_HEADS) / 8, 256>>>(
        encpart, gaq, gak, QAh, KAh, KAl, VAh, VAl);

    // [3] big QKV GEMM (2-pass fp16, fused epilogue)
    gemm_qkv_fused_kernel<<<dim3(INNER3 / 128, S_LEN / 128), 256, QKV_SMEM_BYTES>>>(
        hs_h, w_h + 0 * WS, w_l + 0 * WS,
        gq, gk, rc, rs, QAh, KAh, KAl, VAh, VAl);

    // [4] attention (BQ=128, 256 thr, 2 CTAs/SM)
    attn_mma_kernel<<<dim3(STOT / 128, NJH), 256, ATT_SM_BYTES>>>(
        QAh, KAh, KAl, VAh, VAl, OA, vis_h);

    // [5] text gather
    gather_txt_kernel<<<(T_LEN * INNER / 4) / 256, 256>>>(OA, txt_h, txt_l);

    // [6] vis out GEMM (2-pass, A single)
    gemm_out2_kernel<<<dim3(INNER / 128, S_LEN / 128), 256, QKV_SMEM_BYTES>>>(
        vis_h, w_h + 6 * WS, w_l + 6 * WS, bout, out, S_LEN, INNER, INNER);

    // [7] txt out GEMM (3-pass v2, K-split x4), [8] reduce with bias
    gemm_v2_kernel<<<dim3(INNER / 128, 1, 4), 512, GEMM2_SMEM_BYTES>>>(
        txt_h, txt_l, w_h + 7 * WS, w_l + 7 * WS, txtpart, T_LEN, INNER, INNER, 4);
    reduce4_kernel<<<(T_LEN * INNER / 4) / 256, 256>>>(
        txtpart, baout, out + (size_t)S_LEN * INNER, T_LEN * INNER, INNER);
}